// round 1
// baseline (speedup 1.0000x reference)
#include <cuda_runtime.h>

// ----------------------------------------------------------------------------
// FreeTraj temporal attention, fp32.
//   x:[2560,16,512], Wq/Wk/Wv/Wo:[512,512], bo:[512], rel_k/rel_v:[33,64]
// Pipeline:
//   1) gemm_kernel: qkv[40960,1536] = x[40960,512] @ [Wq|Wk|Wv]
//   2) attn_kernel: per (hw, head) 16x16 attention with rel-pos bias + freetraj mask
//   3) gemm_kernel: out[40960,512] = att[40960,512] @ Wo + bo
// ----------------------------------------------------------------------------

#define HW_N   2560
#define T_LEN  16
#define NHEAD  8
#define DHEAD  64
#define QDIM   512
#define MROWS  (HW_N * T_LEN)   // 40960

__device__ float g_qkv[(size_t)MROWS * 1536];
__device__ float g_att[(size_t)MROWS * 512];

// ---------------------------------------------------------------------------
// Tiled SGEMM: C[M, Ntot] = A[M,512] @ B(column-block-selected) (+ bias)
// B0/B1/B2 are each [512,512] row-major; output column block n0 (multiple of
// 128) selects B = B{n0/512}, inner column = n0 % 512.
// BM=BN=128, BK=16, 256 threads, 8x8 microtile.
// ---------------------------------------------------------------------------
__global__ __launch_bounds__(256) void gemm_kernel(
    const float* __restrict__ A,
    const float* __restrict__ B0,
    const float* __restrict__ B1,
    const float* __restrict__ B2,
    const float* __restrict__ bias,
    float* __restrict__ C,
    int Ntot)
{
    const int K = 512;
    __shared__ float As[16][128];
    __shared__ float Bs[16][128];

    const int tid = threadIdx.x;
    const int m0 = blockIdx.y * 128;
    const int n0 = blockIdx.x * 128;

    const int which = n0 >> 9;
    const float* __restrict__ B = (which == 0) ? B0 : ((which == 1) ? B1 : B2);
    const int nc0 = n0 & 511;

    const int tm = (tid >> 4) * 8;   // row in tile
    const int tn = (tid & 15) * 8;   // col in tile

    float acc[8][8];
#pragma unroll
    for (int i = 0; i < 8; i++)
#pragma unroll
        for (int j = 0; j < 8; j++) acc[i][j] = 0.f;

    // load mappings
    const int ar = tid >> 2;          // 0..63 (+64)
    const int ac = (tid & 3) * 4;     // k within 16
    const int br = tid >> 5;          // 0..7 (+8)
    const int bc = (tid & 31) * 4;    // col within 128

    for (int k0 = 0; k0 < K; k0 += 16) {
#pragma unroll
        for (int i = 0; i < 2; i++) {
            const int r = ar + i * 64;
            float4 v = *(const float4*)&A[(size_t)(m0 + r) * K + k0 + ac];
            As[ac + 0][r] = v.x;
            As[ac + 1][r] = v.y;
            As[ac + 2][r] = v.z;
            As[ac + 3][r] = v.w;
        }
#pragma unroll
        for (int i = 0; i < 2; i++) {
            const int r = br + i * 8;
            *(float4*)&Bs[r][bc] =
                *(const float4*)&B[(size_t)(k0 + r) * 512 + nc0 + bc];
        }
        __syncthreads();

#pragma unroll
        for (int k = 0; k < 16; k++) {
            float a[8], b[8];
            *(float4*)&a[0] = *(float4*)&As[k][tm];
            *(float4*)&a[4] = *(float4*)&As[k][tm + 4];
            *(float4*)&b[0] = *(float4*)&Bs[k][tn];
            *(float4*)&b[4] = *(float4*)&Bs[k][tn + 4];
#pragma unroll
            for (int i = 0; i < 8; i++)
#pragma unroll
                for (int j = 0; j < 8; j++)
                    acc[i][j] += a[i] * b[j];
        }
        __syncthreads();
    }

    // epilogue
    float badd[8];
#pragma unroll
    for (int j = 0; j < 8; j++)
        badd[j] = bias ? bias[n0 + tn + j] : 0.f;

#pragma unroll
    for (int i = 0; i < 8; i++) {
        float4 v0 = make_float4(acc[i][0] + badd[0], acc[i][1] + badd[1],
                                acc[i][2] + badd[2], acc[i][3] + badd[3]);
        float4 v1 = make_float4(acc[i][4] + badd[4], acc[i][5] + badd[5],
                                acc[i][6] + badd[6], acc[i][7] + badd[7]);
        float* cp = &C[(size_t)(m0 + tm + i) * Ntot + n0 + tn];
        *(float4*)&cp[0] = v0;
        *(float4*)&cp[4] = v1;
    }
}

// ---------------------------------------------------------------------------
// Attention kernel: one block per (head, hw). 128 threads.
//   sim[t][s] = (q[t].k[s] + q[t].rel_k[s-t+16]) * 0.125 * mask(t,s)
//   mask(t,s) = (fg_t == fg_s) ? 1.0 : 0.01   (freetraj box membership)
//   out[t][d] = sum_s softmax(sim)[t][s] * (v[s][d] + rel_v[s-t+16][d])
// ---------------------------------------------------------------------------
__global__ __launch_bounds__(128) void attn_kernel(
    const float* __restrict__ qkv,
    const float* __restrict__ rel_k,
    const float* __restrict__ rel_v,
    float* __restrict__ att_out)
{
    const int h  = blockIdx.x;   // 0..7
    const int hw = blockIdx.y;   // 0..2559
    const int tid = threadIdx.x; // 0..127

    __shared__ float qs[16][64];
    __shared__ float ks[16][64];
    __shared__ float vs[16][64];
    __shared__ float rks[33][64];
    __shared__ float rvs[33][64];
    __shared__ float sim[16][17];
    __shared__ float attn[16][17];

    const float* base = qkv + (size_t)hw * T_LEN * 1536 + h * DHEAD;
    const int r  = tid >> 3;        // 0..15 (row t)
    const int c0 = (tid & 7) * 8;   // 0..56 (col base)

    // load q,k,v tiles (16x64 each) as float4
#pragma unroll
    for (int j = 0; j < 2; j++) {
        *(float4*)&qs[r][c0 + 4 * j] =
            *(const float4*)&base[(size_t)r * 1536 + c0 + 4 * j];
        *(float4*)&ks[r][c0 + 4 * j] =
            *(const float4*)&base[(size_t)r * 1536 + 512 + c0 + 4 * j];
        *(float4*)&vs[r][c0 + 4 * j] =
            *(const float4*)&base[(size_t)r * 1536 + 1024 + c0 + 4 * j];
    }
    // load rel_k / rel_v (33x64 = 528 float4 each)
    for (int i = tid; i < 33 * 16; i += 128) {
        ((float4*)&rks[0][0])[i] = ((const float4*)rel_k)[i];
        ((float4*)&rvs[0][0])[i] = ((const float4*)rel_v)[i];
    }

    // freetraj fg bitmask for this pixel (replicates Python double math exactly;
    // note int((0.35-0.10)*64)==15 and int((0.35-0.10)*40)==9 in IEEE double)
    const int y  = hw / 40;
    const int xx = hw % 40;
    const int SUBH = (int)((0.35 - 0.10) * 64.0);  // 15
    const int SUBW = (int)((0.35 - 0.10) * 40.0);  // 9
    unsigned fgm = 0;
#pragma unroll
    for (int i = 0; i < 16; i++) {
        double rr = (double)i / 15.0;
        double ph = 0.10 + rr * (0.60 - 0.10);
        double pw = 0.10 + rr * (0.60 - 0.10);
        int hs = (int)(ph * 64.0);
        int ws = (int)(pw * 40.0);
        if (y >= hs && y < hs + SUBH && xx >= ws && xx < ws + SUBW)
            fgm |= (1u << i);
    }

    __syncthreads();

    // scores: 256 (t,s) pairs, 2 per thread
#pragma unroll
    for (int pp = 0; pp < 2; pp++) {
        const int p = tid + pp * 128;
        const int t = p >> 4, s = p & 15;
        const float* rk = rks[s - t + 16];
        float acc = 0.f;
#pragma unroll
        for (int d = 0; d < 64; d++)
            acc += qs[t][d] * (ks[s][d] + rk[d]);
        const float m =
            (((fgm >> t) & 1u) == ((fgm >> s) & 1u)) ? 1.0f : 0.01f;
        sim[t][s] = acc * 0.125f * m;
    }
    __syncthreads();

    // softmax over s (one thread per row)
    if (tid < 16) {
        float mx = -1e30f;
#pragma unroll
        for (int s = 0; s < 16; s++) mx = fmaxf(mx, sim[tid][s]);
        float sum = 0.f;
#pragma unroll
        for (int s = 0; s < 16; s++) {
            float e = expf(sim[tid][s] - mx);
            attn[tid][s] = e;
            sum += e;
        }
        float inv = 1.0f / sum;
#pragma unroll
        for (int s = 0; s < 16; s++) attn[tid][s] *= inv;
    }
    __syncthreads();

    // out[t][c0..c0+7] = sum_s attn[t][s] * (v[s][d] + rel_v[s-t+16][d])
    const int t = r;
    float o[8];
#pragma unroll
    for (int j = 0; j < 8; j++) o[j] = 0.f;
#pragma unroll
    for (int s = 0; s < 16; s++) {
        const float a = attn[t][s];
        const float* rv = rvs[s - t + 16];
#pragma unroll
        for (int j = 0; j < 8; j++)
            o[j] += a * (vs[s][c0 + j] + rv[c0 + j]);
    }
    float* op = &att_out[((size_t)hw * T_LEN + t) * 512 + h * DHEAD + c0];
#pragma unroll
    for (int j = 0; j < 2; j++)
        *(float4*)&op[4 * j] = make_float4(o[4 * j], o[4 * j + 1],
                                           o[4 * j + 2], o[4 * j + 3]);
}

// ---------------------------------------------------------------------------
extern "C" void kernel_launch(void* const* d_in, const int* in_sizes, int n_in,
                              void* d_out, int out_size)
{
    const float* x   = (const float*)d_in[0];
    const float* Wq  = (const float*)d_in[1];
    const float* Wk  = (const float*)d_in[2];
    const float* Wv  = (const float*)d_in[3];
    const float* Wo  = (const float*)d_in[4];
    const float* bo  = (const float*)d_in[5];
    const float* rk  = (const float*)d_in[6];
    const float* rv  = (const float*)d_in[7];
    float* out = (float*)d_out;

    float *qkv = nullptr, *att = nullptr;
    cudaGetSymbolAddress((void**)&qkv, g_qkv);
    cudaGetSymbolAddress((void**)&att, g_att);

    // 1) QKV projection: [40960,512] @ [512,1536]
    gemm_kernel<<<dim3(1536 / 128, MROWS / 128), 256>>>(
        x, Wq, Wk, Wv, nullptr, qkv, 1536);

    // 2) attention per (head, pixel)
    attn_kernel<<<dim3(NHEAD, HW_N), 128>>>(qkv, rk, rv, att);

    // 3) output projection + bias: [40960,512] @ [512,512] + bo
    gemm_kernel<<<dim3(512 / 128, MROWS / 128), 256>>>(
        att, Wo, Wo, Wo, bo, out, 512);
}

// round 6
// speedup vs baseline: 1.9120x; 1.9120x over previous
#include <cuda_runtime.h>
#include <cuda_bf16.h>
#include <cstdint>

// ----------------------------------------------------------------------------
// FreeTraj temporal attention. GEMMs via baseline-PTX bf16 mma.sync (HMMA),
// 3-term bf16 split for fp32-class accuracy:
//   a*b ~= hiA*hiB + hiA*loB + loA*hiB  (drop loA*loB, ~2^-16 rel)
//   A_cat = [hi|hi|lo] (K=1536), B_cat = [hi|lo|hi]  -> one bf16 GEMM, K=1536.
// Pipeline:
//   split_x : x fp32 -> x_cat bf16 [40960,1536]
//   split_w1: Wq|Wk|Wv^T -> w1_cat bf16 [1536,1536]
//   split_w2: Wo^T       -> w2_cat bf16 [512,1536]
//   mma_gemm: qkv fp32 [40960,1536] = x_cat @ w1_cat^T
//   attn    : 16x16 attention per (hw,head) -> a_cat bf16 split [40960,1536]
//   mma_gemm: out fp32 [40960,512] = a_cat @ w2_cat^T + bo
// ----------------------------------------------------------------------------

#define HW_N   2560
#define T_LEN  16
#define NHEAD  8
#define DHEAD  64
#define MROWS  (HW_N * T_LEN)   // 40960
#define KCAT   1536

#define BM 128
#define BN 128
#define BK 64
#define NKI (KCAT / BK)          // 24
#define STAGE_BYTES 32768        // A 16KB + B 16KB
#define SMEM_TOTAL (3 * STAGE_BYTES)

__device__ float         g_qkv[(size_t)MROWS * 1536];
__device__ __nv_bfloat16 g_xcat[(size_t)MROWS * KCAT];
__device__ __nv_bfloat16 g_acat[(size_t)MROWS * KCAT];
__device__ __nv_bfloat16 g_w1[(size_t)1536 * KCAT];
__device__ __nv_bfloat16 g_w2[(size_t)512 * KCAT];

// ------------------------------- helpers -----------------------------------
__device__ __forceinline__ uint32_t smem_u32(const void* p) {
    uint32_t a;
    asm("{ .reg .u64 t; cvta.to.shared.u64 t, %1; cvt.u32.u64 %0, t; }"
        : "=r"(a) : "l"(p));
    return a;
}
#define CP_ASYNC16(sa, gp) \
    asm volatile("cp.async.cg.shared.global [%0], [%1], 16;" \
                 :: "r"(sa), "l"(gp))
#define CP_COMMIT() asm volatile("cp.async.commit_group;" ::: "memory")

__device__ __forceinline__ void ldsm4(uint32_t* r, uint32_t addr) {
    asm volatile("ldmatrix.sync.aligned.m8n8.x4.shared.b16 {%0,%1,%2,%3}, [%4];"
                 : "=r"(r[0]), "=r"(r[1]), "=r"(r[2]), "=r"(r[3]) : "r"(addr));
}
__device__ __forceinline__ void mma16816(float* d, const uint32_t* a,
                                         const uint32_t* b) {
    asm volatile(
        "mma.sync.aligned.m16n8k16.row.col.f32.bf16.bf16.f32 "
        "{%0,%1,%2,%3}, {%4,%5,%6,%7}, {%8,%9}, {%0,%1,%2,%3};"
        : "+f"(d[0]), "+f"(d[1]), "+f"(d[2]), "+f"(d[3])
        : "r"(a[0]), "r"(a[1]), "r"(a[2]), "r"(a[3]), "r"(b[0]), "r"(b[1]));
}

// ---------------------------------------------------------------------------
// bf16 GEMM: C[M, Ntot] fp32 = A[M,1536] @ B[Ntot,1536]^T (+bias)
// CTA 128x128, BK=64, 3-stage cp.async, 4 warps of 64x64 (2x2 grid).
// smem rows are 128B (64 bf16), XOR-8 swizzled 16B chunks.
// ---------------------------------------------------------------------------
__global__ __launch_bounds__(128, 2) void mma_gemm(
    const __nv_bfloat16* __restrict__ A,
    const __nv_bfloat16* __restrict__ B,
    const float* __restrict__ bias,
    float* __restrict__ C,
    int Ntot)
{
    extern __shared__ char smem[];
    const uint32_t sb = smem_u32(smem);
    const int tid = threadIdx.x;
    const int l = tid & 31, w = tid >> 5;
    const int wm = (w >> 1) << 6;       // warp m offset: 0 / 64
    const int wn = (w & 1) << 6;        // warp n offset: 0 / 64
    const size_t m0 = (size_t)blockIdx.y * BM;
    const size_t n0 = (size_t)blockIdx.x * BN;

    // cp.async per-thread mapping: 8 A chunks + 8 B chunks of 16B per stage
    uint32_t stA[8], stB[8];
    const __nv_bfloat16 *gA[8], *gB[8];
#pragma unroll
    for (int i = 0; i < 8; i++) {
        const int id = i * 128 + tid;
        const int row = id >> 3, kc = id & 7;
        const uint32_t so = (uint32_t)(row * 128 + ((kc ^ (row & 7)) << 4));
        stA[i] = so;
        stB[i] = so + 16384;
        gA[i] = A + (m0 + row) * KCAT + kc * 8;
        gB[i] = B + (n0 + row) * KCAT + kc * 8;
    }

#define LOAD_STAGE(s, c) do {                                   \
    const uint32_t _b = sb + (uint32_t)(s) * STAGE_BYTES;       \
    const size_t _ko = (size_t)(c) * BK;                        \
    _Pragma("unroll")                                           \
    for (int _i = 0; _i < 8; _i++) CP_ASYNC16(_b + stA[_i], gA[_i] + _ko); \
    _Pragma("unroll")                                           \
    for (int _i = 0; _i < 8; _i++) CP_ASYNC16(_b + stB[_i], gB[_i] + _ko); \
    CP_COMMIT();                                                \
} while (0)

    LOAD_STAGE(0, 0);
    LOAD_STAGE(1, 1);

    // ldmatrix lane addressing
    const int arow = wm + (l & 15);          // m row within tile
    const int kadd_a = (l >> 4) & 1;         // second k8 half
    const int brow = wn + (l & 7) + ((l & 16) >> 1);  // n row within tile
    const int kadd_b = (l >> 3) & 1;
    const int axor = arow & 7, bxor = brow & 7;

    float acc[4][8][4];
#pragma unroll
    for (int i = 0; i < 4; i++)
#pragma unroll
        for (int j = 0; j < 8; j++)
#pragma unroll
            for (int q = 0; q < 4; q++) acc[i][j][q] = 0.f;

    for (int c = 0; c < NKI; c++) {
        if (c < NKI - 1) asm volatile("cp.async.wait_group 1;" ::: "memory");
        else             asm volatile("cp.async.wait_group 0;" ::: "memory");
        __syncthreads();
        if (c + 2 < NKI) LOAD_STAGE((c + 2) % 3, c + 2);

        const uint32_t base = sb + (uint32_t)(c % 3) * STAGE_BYTES;
#pragma unroll
        for (int ks = 0; ks < 4; ks++) {
            const uint32_t kca = (uint32_t)((ks * 2 + kadd_a) ^ axor) << 4;
            const uint32_t kcb = (uint32_t)((ks * 2 + kadd_b) ^ bxor) << 4;
            uint32_t af[4][4], bf[4][4];
#pragma unroll
            for (int im = 0; im < 4; im++)
                ldsm4(af[im], base + (uint32_t)(arow + im * 16) * 128 + kca);
#pragma unroll
            for (int jn = 0; jn < 4; jn++)
                ldsm4(bf[jn], base + 16384 +
                              (uint32_t)(brow + jn * 16) * 128 + kcb);
#pragma unroll
            for (int im = 0; im < 4; im++)
#pragma unroll
                for (int j = 0; j < 8; j++)
                    mma16816(acc[im][j], af[im], &bf[j >> 1][(j & 1) * 2]);
        }
    }

    // epilogue: direct stores (float2 per lane)
#pragma unroll
    for (int im = 0; im < 4; im++) {
        const size_t r_ = m0 + wm + im * 16 + (l >> 2);
#pragma unroll
        for (int j = 0; j < 8; j++) {
            const size_t c_ = n0 + wn + j * 8 + ((l & 3) << 1);
            float bx = 0.f, by = 0.f;
            if (bias) { bx = bias[c_]; by = bias[c_ + 1]; }
            float2 v0 = make_float2(acc[im][j][0] + bx, acc[im][j][1] + by);
            float2 v1 = make_float2(acc[im][j][2] + bx, acc[im][j][3] + by);
            *(float2*)&C[r_ * Ntot + c_] = v0;
            *(float2*)&C[(r_ + 8) * Ntot + c_] = v1;
        }
    }
#undef LOAD_STAGE
}

// ---------------------------------------------------------------------------
// Split conversions
// ---------------------------------------------------------------------------
__global__ void split_x(const float* __restrict__ src, __nv_bfloat16* __restrict__ dst)
{
    const int idx = blockIdx.x * blockDim.x + threadIdx.x;  // over MROWS*128
    if (idx >= MROWS * 128) return;
    const int m = idx >> 7, k4 = idx & 127;
    float4 v = ((const float4*)src)[idx];
    __nv_bfloat16 h[4], l[4];
    float f[4] = {v.x, v.y, v.z, v.w};
#pragma unroll
    for (int i = 0; i < 4; i++) {
        h[i] = __float2bfloat16(f[i]);
        l[i] = __float2bfloat16(f[i] - __bfloat162float(h[i]));
    }
    __nv_bfloat16* d = dst + (size_t)m * KCAT + k4 * 4;
    uint2 hp, lp;
    memcpy(&hp, h, 8); memcpy(&lp, l, 8);
    *(uint2*)(d)        = hp;   // hi
    *(uint2*)(d + 512)  = hp;   // hi
    *(uint2*)(d + 1024) = lp;   // lo
}

__global__ void split_w1(const float* __restrict__ Wq, const float* __restrict__ Wk,
                         const float* __restrict__ Wv, __nv_bfloat16* __restrict__ dst)
{
    const int n = blockIdx.x;  // 0..1535 output column -> B row
    const float* W = (n < 512) ? Wq : ((n < 1024) ? Wk : Wv);
    const int nc = n & 511;
    for (int k = threadIdx.x; k < 512; k += blockDim.x) {
        const float v = W[(size_t)k * 512 + nc];
        __nv_bfloat16 h = __float2bfloat16(v);
        __nv_bfloat16 l = __float2bfloat16(v - __bfloat162float(h));
        dst[(size_t)n * KCAT + k]        = h;  // hi
        dst[(size_t)n * KCAT + 512 + k]  = l;  // lo
        dst[(size_t)n * KCAT + 1024 + k] = h;  // hi
    }
}

__global__ void split_w2(const float* __restrict__ Wo, __nv_bfloat16* __restrict__ dst)
{
    const int n = blockIdx.x;  // 0..511
    for (int k = threadIdx.x; k < 512; k += blockDim.x) {
        const float v = Wo[(size_t)k * 512 + n];
        __nv_bfloat16 h = __float2bfloat16(v);
        __nv_bfloat16 l = __float2bfloat16(v - __bfloat162float(h));
        dst[(size_t)n * KCAT + k]        = h;
        dst[(size_t)n * KCAT + 512 + k]  = l;
        dst[(size_t)n * KCAT + 1024 + k] = h;
    }
}

// ---------------------------------------------------------------------------
// Attention: one block per (head, hw); outputs bf16 split [hi|hi|lo].
// ---------------------------------------------------------------------------
__global__ __launch_bounds__(128) void attn_kernel(
    const float* __restrict__ qkv,
    const float* __restrict__ rel_k,
    const float* __restrict__ rel_v,
    __nv_bfloat16* __restrict__ a_cat)
{
    const int h  = blockIdx.x;
    const int hw = blockIdx.y;
    const int tid = threadIdx.x;

    __shared__ float qs[16][64];
    __shared__ float ks[16][64];
    __shared__ float vs[16][64];
    __shared__ float rks[33][64];
    __shared__ float rvs[33][64];
    __shared__ float sim[16][17];
    __shared__ float attn[16][17];

    const float* base = qkv + (size_t)hw * T_LEN * 1536 + h * DHEAD;
    const int r  = tid >> 3;
    const int c0 = (tid & 7) * 8;

#pragma unroll
    for (int j = 0; j < 2; j++) {
        *(float4*)&qs[r][c0 + 4 * j] = *(const float4*)&base[(size_t)r * 1536 + c0 + 4 * j];
        *(float4*)&ks[r][c0 + 4 * j] = *(const float4*)&base[(size_t)r * 1536 + 512 + c0 + 4 * j];
        *(float4*)&vs[r][c0 + 4 * j] = *(const float4*)&base[(size_t)r * 1536 + 1024 + c0 + 4 * j];
    }
    for (int i = tid; i < 33 * 16; i += 128) {
        ((float4*)&rks[0][0])[i] = ((const float4*)rel_k)[i];
        ((float4*)&rvs[0][0])[i] = ((const float4*)rel_v)[i];
    }

    // freetraj fg bitmask (exact Python double math; int((0.35-0.10)*64)==15, *40==9)
    const int y  = hw / 40;
    const int xx = hw % 40;
    const int SUBH = (int)((0.35 - 0.10) * 64.0);
    const int SUBW = (int)((0.35 - 0.10) * 40.0);
    unsigned fgm = 0;
#pragma unroll
    for (int i = 0; i < 16; i++) {
        double rr = (double)i / 15.0;
        double ph = 0.10 + rr * (0.60 - 0.10);
        double pw = 0.10 + rr * (0.60 - 0.10);
        int hs = (int)(ph * 64.0);
        int ws = (int)(pw * 40.0);
        if (y >= hs && y < hs + SUBH && xx >= ws && xx < ws + SUBW)
            fgm |= (1u << i);
    }
    __syncthreads();

#pragma unroll
    for (int pp = 0; pp < 2; pp++) {
        const int p = tid + pp * 128;
        const int t = p >> 4, s = p & 15;
        const float* rk = rks[s - t + 16];
        float acc = 0.f;
#pragma unroll
        for (int d = 0; d < 64; d++)
            acc += qs[t][d] * (ks[s][d] + rk[d]);
        const float m = (((fgm >> t) & 1u) == ((fgm >> s) & 1u)) ? 1.0f : 0.01f;
        sim[t][s] = acc * 0.125f * m;
    }
    __syncthreads();

    if (tid < 16) {
        float mx = -1e30f;
#pragma unroll
        for (int s = 0; s < 16; s++) mx = fmaxf(mx, sim[tid][s]);
        float sum = 0.f;
#pragma unroll
        for (int s = 0; s < 16; s++) {
            float e = expf(sim[tid][s] - mx);
            attn[tid][s] = e;
            sum += e;
        }
        float inv = 1.0f / sum;
#pragma unroll
        for (int s = 0; s < 16; s++) attn[tid][s] *= inv;
    }
    __syncthreads();

    const int t = r;
    float o[8];
#pragma unroll
    for (int j = 0; j < 8; j++) o[j] = 0.f;
#pragma unroll
    for (int s = 0; s < 16; s++) {
        const float a = attn[t][s];
        const float* rv = rvs[s - t + 16];
#pragma unroll
        for (int j = 0; j < 8; j++)
            o[j] += a * (vs[s][c0 + j] + rv[c0 + j]);
    }

    // bf16 split store: [hi | hi | lo]
    __nv_bfloat16 hb[8], lb[8];
#pragma unroll
    for (int j = 0; j < 8; j++) {
        hb[j] = __float2bfloat16(o[j]);
        lb[j] = __float2bfloat16(o[j] - __bfloat162float(hb[j]));
    }
    __nv_bfloat16* op = a_cat + ((size_t)hw * T_LEN + t) * KCAT + h * DHEAD + c0;
    uint4 hp, lp;
    memcpy(&hp, hb, 16); memcpy(&lp, lb, 16);
    *(uint4*)(op)        = hp;
    *(uint4*)(op + 512)  = hp;
    *(uint4*)(op + 1024) = lp;
}

// ---------------------------------------------------------------------------
extern "C" void kernel_launch(void* const* d_in, const int* in_sizes, int n_in,
                              void* d_out, int out_size)
{
    const float* x   = (const float*)d_in[0];
    const float* Wq  = (const float*)d_in[1];
    const float* Wk  = (const float*)d_in[2];
    const float* Wv  = (const float*)d_in[3];
    const float* Wo  = (const float*)d_in[4];
    const float* bo  = (const float*)d_in[5];
    const float* rk  = (const float*)d_in[6];
    const float* rv  = (const float*)d_in[7];
    float* out = (float*)d_out;

    float *qkv = nullptr;
    __nv_bfloat16 *xcat = nullptr, *acat = nullptr, *w1 = nullptr, *w2 = nullptr;
    cudaGetSymbolAddress((void**)&qkv, g_qkv);
    cudaGetSymbolAddress((void**)&xcat, g_xcat);
    cudaGetSymbolAddress((void**)&acat, g_acat);
    cudaGetSymbolAddress((void**)&w1, g_w1);
    cudaGetSymbolAddress((void**)&w2, g_w2);

    cudaFuncSetAttribute(mma_gemm, cudaFuncAttributeMaxDynamicSharedMemorySize,
                         SMEM_TOTAL);

    // conversions
    split_x<<<(MROWS * 128 + 255) / 256, 256>>>(x, xcat);
    split_w1<<<1536, 128>>>(Wq, Wk, Wv, w1);
    split_w2<<<512, 128>>>(Wo, w2);

    // QKV projection: [40960,1536] = x_cat @ w1^T
    mma_gemm<<<dim3(1536 / BN, MROWS / BM), 128, SMEM_TOTAL>>>(
        xcat, w1, nullptr, qkv, 1536);

    // attention
    attn_kernel<<<dim3(NHEAD, HW_N), 128>>>(qkv, rk, rv, acat);

    // output projection: [40960,512] = a_cat @ w2^T + bo
    mma_gemm<<<dim3(512 / BN, MROWS / BM), 128, SMEM_TOTAL>>>(
        acat, w2, bo, out, 512);
}

// round 9
// speedup vs baseline: 2.9418x; 1.5386x over previous
#include <cuda_runtime.h>
#include <cuda_bf16.h>
#include <cstdint>

// ----------------------------------------------------------------------------
// FreeTraj temporal attention. GEMMs via baseline-PTX bf16 mma.sync (HMMA),
// 3-term bf16 split: a*b ~= hiA*hiB + hiA*loB + loA*hiB  (logical K=1536).
// Physical storage dedup: A phys [hi|lo] (K=1024), logical segs {hi,hi,lo};
//                         B phys [hi|lo] (K=1024), logical segs {hi,lo,hi}.
// Pipeline:
//   split_x : x fp32 -> x_cat bf16 [40960,1024]
//   split_w1: Wq|Wk|Wv^T -> w1 bf16 [1536,1024]
//   split_w2: Wo^T       -> w2 bf16 [512,1024]
//   mma_gemm: qkv fp32 [40960,1536] = x_cat @ w1^T (logical K=1536)
//   attn    : 16x16 attention per (hw,head) -> a_cat bf16 [40960,1024]
//   mma_gemm: out fp32 [40960,512] = a_cat @ w2^T + bo
// ----------------------------------------------------------------------------

#define HW_N   2560
#define T_LEN  16
#define NHEAD  8
#define DHEAD  64
#define MROWS  (HW_N * T_LEN)   // 40960
#define KPHYS  1024             // physical row stride (bf16 elements)
#define NKI    24               // logical K chunks of 64 (24*64 = 1536)

#define BM 128
#define BN 128
#define BK 64
#define STAGE_BYTES 32768        // A 16KB + B 16KB
#define SMEM_TOTAL (3 * STAGE_BYTES)

__device__ float         g_qkv[(size_t)MROWS * 1536];
__device__ __nv_bfloat16 g_xcat[(size_t)MROWS * KPHYS];
__device__ __nv_bfloat16 g_acat[(size_t)MROWS * KPHYS];
__device__ __nv_bfloat16 g_w1[(size_t)1536 * KPHYS];
__device__ __nv_bfloat16 g_w2[(size_t)512 * KPHYS];

// ------------------------------- helpers -----------------------------------
__device__ __forceinline__ uint32_t smem_u32(const void* p) {
    uint32_t a;
    asm("{ .reg .u64 t; cvta.to.shared.u64 t, %1; cvt.u32.u64 %0, t; }"
        : "=r"(a) : "l"(p));
    return a;
}
#define CP_ASYNC16(sa, gp) \
    asm volatile("cp.async.cg.shared.global [%0], [%1], 16;" \
                 :: "r"(sa), "l"(gp))
#define CP_COMMIT() asm volatile("cp.async.commit_group;" ::: "memory")

__device__ __forceinline__ void ldsm4(uint32_t* r, uint32_t addr) {
    asm volatile("ldmatrix.sync.aligned.m8n8.x4.shared.b16 {%0,%1,%2,%3}, [%4];"
                 : "=r"(r[0]), "=r"(r[1]), "=r"(r[2]), "=r"(r[3]) : "r"(addr));
}
__device__ __forceinline__ void mma16816(float* d, const uint32_t* a,
                                         const uint32_t* b) {
    asm volatile(
        "mma.sync.aligned.m16n8k16.row.col.f32.bf16.bf16.f32 "
        "{%0,%1,%2,%3}, {%4,%5,%6,%7}, {%8,%9}, {%0,%1,%2,%3};"
        : "+f"(d[0]), "+f"(d[1]), "+f"(d[2]), "+f"(d[3])
        : "r"(a[0]), "r"(a[1]), "r"(a[2]), "r"(b[0]), "r"(b[1]), "r"(a[3]) );
}

// logical chunk -> physical bf16 offset within a row
__device__ __forceinline__ int ko_a(int c) {   // A segs: hi,hi,lo
    return ((c >> 3) == 2 ? 512 : 0) + (c & 7) * 64;
}
__device__ __forceinline__ int ko_b(int c) {   // B segs: hi,lo,hi
    return ((c >> 3) == 1 ? 512 : 0) + (c & 7) * 64;
}

// ---------------------------------------------------------------------------
// bf16 GEMM: C[M, Ntot] fp32 = A @ B^T (+bias), logical K=1536 over phys 1024.
// CTA 128x128, BK=64, 3-stage cp.async, 4 warps of 64x64 (2x2 grid).
// smem rows 128B (64 bf16), XOR-8 swizzled 16B chunks.
// ---------------------------------------------------------------------------
__global__ __launch_bounds__(128, 2) void mma_gemm(
    const __nv_bfloat16* __restrict__ A,
    const __nv_bfloat16* __restrict__ B,
    const float* __restrict__ bias,
    float* __restrict__ C,
    int Ntot)
{
    extern __shared__ char smem[];
    const uint32_t sb = smem_u32(smem);
    const int tid = threadIdx.x;
    const int l = tid & 31, w = tid >> 5;
    const int wm = (w >> 1) << 6;
    const int wn = (w & 1) << 6;
    const size_t m0 = (size_t)blockIdx.y * BM;
    const size_t n0 = (size_t)blockIdx.x * BN;

    // cp.async per-thread mapping: 8 A chunks + 8 B chunks of 16B per stage
    uint32_t stA[8], stB[8];
    const __nv_bfloat16 *gA[8], *gB[8];
#pragma unroll
    for (int i = 0; i < 8; i++) {
        const int id = i * 128 + tid;
        const int row = id >> 3, kc = id & 7;
        const uint32_t so = (uint32_t)(row * 128 + ((kc ^ (row & 7)) << 4));
        stA[i] = so;
        stB[i] = so + 16384;
        gA[i] = A + (m0 + row) * KPHYS + kc * 8;
        gB[i] = B + (n0 + row) * KPHYS + kc * 8;
    }

#define LOAD_STAGE(s, c) do {                                   \
    const uint32_t _b = sb + (uint32_t)(s) * STAGE_BYTES;       \
    const int _ka = ko_a(c), _kb = ko_b(c);                     \
    _Pragma("unroll")                                           \
    for (int _i = 0; _i < 8; _i++) CP_ASYNC16(_b + stA[_i], gA[_i] + _ka); \
    _Pragma("unroll")                                           \
    for (int _i = 0; _i < 8; _i++) CP_ASYNC16(_b + stB[_i], gB[_i] + _kb); \
    CP_COMMIT();                                                \
} while (0)

    LOAD_STAGE(0, 0);
    LOAD_STAGE(1, 1);

    // ldmatrix lane addressing
    const int arow = wm + (l & 15);
    const int kadd_a = (l >> 4) & 1;
    const int brow = wn + (l & 7) + ((l & 16) >> 1);
    const int kadd_b = (l >> 3) & 1;
    const int axor = arow & 7, bxor = brow & 7;

    float acc[4][8][4];
#pragma unroll
    for (int i = 0; i < 4; i++)
#pragma unroll
        for (int j = 0; j < 8; j++)
#pragma unroll
            for (int q = 0; q < 4; q++) acc[i][j][q] = 0.f;

    for (int c = 0; c < NKI; c++) {
        if (c < NKI - 1) asm volatile("cp.async.wait_group 1;" ::: "memory");
        else             asm volatile("cp.async.wait_group 0;" ::: "memory");
        __syncthreads();
        if (c + 2 < NKI) LOAD_STAGE((c + 2) % 3, c + 2);

        const uint32_t base = sb + (uint32_t)(c % 3) * STAGE_BYTES;
#pragma unroll
        for (int ks = 0; ks < 4; ks++) {
            const uint32_t kca = (uint32_t)((ks * 2 + kadd_a) ^ axor) << 4;
            const uint32_t kcb = (uint32_t)((ks * 2 + kadd_b) ^ bxor) << 4;
            uint32_t af[4][4], bf[4][4];
#pragma unroll
            for (int im = 0; im < 4; im++)
                ldsm4(af[im], base + (uint32_t)(arow + im * 16) * 128 + kca);
#pragma unroll
            for (int jn = 0; jn < 4; jn++)
                ldsm4(bf[jn], base + 16384 +
                              (uint32_t)(brow + jn * 16) * 128 + kcb);
#pragma unroll
            for (int im = 0; im < 4; im++)
#pragma unroll
                for (int j = 0; j < 8; j++) {
                    // mma expects a[4] contiguous; keep original order
                    uint32_t aa[4] = {af[im][0], af[im][1], af[im][2], af[im][3]};
                    const uint32_t* bb = &bf[j >> 1][(j & 1) * 2];
                    asm volatile(
                        "mma.sync.aligned.m16n8k16.row.col.f32.bf16.bf16.f32 "
                        "{%0,%1,%2,%3}, {%4,%5,%6,%7}, {%8,%9}, {%0,%1,%2,%3};"
                        : "+f"(acc[im][j][0]), "+f"(acc[im][j][1]),
                          "+f"(acc[im][j][2]), "+f"(acc[im][j][3])
                        : "r"(aa[0]), "r"(aa[1]), "r"(aa[2]), "r"(aa[3]),
                          "r"(bb[0]), "r"(bb[1]));
                }
        }
    }

    // epilogue: direct stores (float2 per lane)
#pragma unroll
    for (int im = 0; im < 4; im++) {
        const size_t r_ = m0 + wm + im * 16 + (l >> 2);
#pragma unroll
        for (int j = 0; j < 8; j++) {
            const size_t c_ = n0 + wn + j * 8 + ((l & 3) << 1);
            float bx = 0.f, by = 0.f;
            if (bias) { bx = bias[c_]; by = bias[c_ + 1]; }
            float2 v0 = make_float2(acc[im][j][0] + bx, acc[im][j][1] + by);
            float2 v1 = make_float2(acc[im][j][2] + bx, acc[im][j][3] + by);
            *(float2*)&C[r_ * Ntot + c_] = v0;
            *(float2*)&C[(r_ + 8) * Ntot + c_] = v1;
        }
    }
#undef LOAD_STAGE
}

// ---------------------------------------------------------------------------
// Split conversions (physical [hi|lo], K=1024)
// ---------------------------------------------------------------------------
__global__ void split_x(const float* __restrict__ src, __nv_bfloat16* __restrict__ dst)
{
    const int idx = blockIdx.x * blockDim.x + threadIdx.x;  // over MROWS*128
    if (idx >= MROWS * 128) return;
    const int m = idx >> 7, k4 = idx & 127;
    float4 v = ((const float4*)src)[idx];
    __nv_bfloat16 h[4], l[4];
    float f[4] = {v.x, v.y, v.z, v.w};
#pragma unroll
    for (int i = 0; i < 4; i++) {
        h[i] = __float2bfloat16(f[i]);
        l[i] = __float2bfloat16(f[i] - __bfloat162float(h[i]));
    }
    __nv_bfloat16* d = dst + (size_t)m * KPHYS + k4 * 4;
    uint2 hp, lp;
    memcpy(&hp, h, 8); memcpy(&lp, l, 8);
    *(uint2*)(d)       = hp;   // hi
    *(uint2*)(d + 512) = lp;   // lo
}

__global__ void split_w1(const float* __restrict__ Wq, const float* __restrict__ Wk,
                         const float* __restrict__ Wv, __nv_bfloat16* __restrict__ dst)
{
    const int n = blockIdx.x;  // 0..1535 output column -> B row
    const float* W = (n < 512) ? Wq : ((n < 1024) ? Wk : Wv);
    const int nc = n & 511;
    for (int k = threadIdx.x; k < 512; k += blockDim.x) {
        const float v = W[(size_t)k * 512 + nc];
        __nv_bfloat16 h = __float2bfloat16(v);
        __nv_bfloat16 l = __float2bfloat16(v - __bfloat162float(h));
        dst[(size_t)n * KPHYS + k]       = h;
        dst[(size_t)n * KPHYS + 512 + k] = l;
    }
}

__global__ void split_w2(const float* __restrict__ Wo, __nv_bfloat16* __restrict__ dst)
{
    const int n = blockIdx.x;  // 0..511
    for (int k = threadIdx.x; k < 512; k += blockDim.x) {
        const float v = Wo[(size_t)k * 512 + n];
        __nv_bfloat16 h = __float2bfloat16(v);
        __nv_bfloat16 l = __float2bfloat16(v - __bfloat162float(h));
        dst[(size_t)n * KPHYS + k]       = h;
        dst[(size_t)n * KPHYS + 512 + k] = l;
    }
}

// ---------------------------------------------------------------------------
// Attention: one block per (head, hw); outputs bf16 split [hi|lo] (K=1024).
// smem arrays padded to stride 65 -> conflict-free score loop.
// ---------------------------------------------------------------------------
#define APAD 65
__global__ __launch_bounds__(128) void attn_kernel(
    const float* __restrict__ qkv,
    const float* __restrict__ rel_k,
    const float* __restrict__ rel_v,
    __nv_bfloat16* __restrict__ a_cat)
{
    const int h  = blockIdx.x;
    const int hw = blockIdx.y;
    const int tid = threadIdx.x;

    __shared__ float qs[16][APAD];
    __shared__ float ks[16][APAD];
    __shared__ float vs[16][APAD];
    __shared__ float rks[33][APAD];
    __shared__ float rvs[33][APAD];
    __shared__ float sim[16][17];
    __shared__ float attn[16][17];

    const float* base = qkv + (size_t)hw * T_LEN * 1536 + h * DHEAD;
    const int r  = tid >> 3;
    const int c0 = (tid & 7) * 8;

#pragma unroll
    for (int j = 0; j < 2; j++) {
        float4 a = *(const float4*)&base[(size_t)r * 1536 + c0 + 4 * j];
        float4 b = *(const float4*)&base[(size_t)r * 1536 + 512 + c0 + 4 * j];
        float4 c = *(const float4*)&base[(size_t)r * 1536 + 1024 + c0 + 4 * j];
        qs[r][c0 + 4 * j + 0] = a.x; qs[r][c0 + 4 * j + 1] = a.y;
        qs[r][c0 + 4 * j + 2] = a.z; qs[r][c0 + 4 * j + 3] = a.w;
        ks[r][c0 + 4 * j + 0] = b.x; ks[r][c0 + 4 * j + 1] = b.y;
        ks[r][c0 + 4 * j + 2] = b.z; ks[r][c0 + 4 * j + 3] = b.w;
        vs[r][c0 + 4 * j + 0] = c.x; vs[r][c0 + 4 * j + 1] = c.y;
        vs[r][c0 + 4 * j + 2] = c.z; vs[r][c0 + 4 * j + 3] = c.w;
    }
    for (int i = tid; i < 33 * 16; i += 128) {
        const int row = i >> 4, q4 = (i & 15) * 4;
        float4 a = ((const float4*)rel_k)[i];
        float4 b = ((const float4*)rel_v)[i];
        rks[row][q4 + 0] = a.x; rks[row][q4 + 1] = a.y;
        rks[row][q4 + 2] = a.z; rks[row][q4 + 3] = a.w;
        rvs[row][q4 + 0] = b.x; rvs[row][q4 + 1] = b.y;
        rvs[row][q4 + 2] = b.z; rvs[row][q4 + 3] = b.w;
    }

    // freetraj fg bitmask (exact Python double math; int((0.35-0.10)*64)==15, *40==9)
    const int y  = hw / 40;
    const int xx = hw % 40;
    const int SUBH = (int)((0.35 - 0.10) * 64.0);
    const int SUBW = (int)((0.35 - 0.10) * 40.0);
    unsigned fgm = 0;
#pragma unroll
    for (int i = 0; i < 16; i++) {
        double rr = (double)i / 15.0;
        double ph = 0.10 + rr * (0.60 - 0.10);
        double pw = 0.10 + rr * (0.60 - 0.10);
        int hs = (int)(ph * 64.0);
        int ws = (int)(pw * 40.0);
        if (y >= hs && y < hs + SUBH && xx >= ws && xx < ws + SUBW)
            fgm |= (1u << i);
    }
    __syncthreads();

#pragma unroll
    for (int pp = 0; pp < 2; pp++) {
        const int p = tid + pp * 128;
        const int t = p >> 4, s = p & 15;
        const float* rk = rks[s - t + 16];
        float acc = 0.f;
#pragma unroll
        for (int d = 0; d < 64; d++)
            acc += qs[t][d] * (ks[s][d] + rk[d]);
        const float m = (((fgm >> t) & 1u) == ((fgm >> s) & 1u)) ? 1.0f : 0.01f;
        sim[t][s] = acc * 0.125f * m;
    }
    __syncthreads();

    if (tid < 16) {
        float mx = -1e30f;
#pragma unroll
        for (int s = 0; s < 16; s++) mx = fmaxf(mx, sim[tid][s]);
        float sum = 0.f;
#pragma unroll
        for (int s = 0; s < 16; s++) {
            float e = expf(sim[tid][s] - mx);
            attn[tid][s] = e;
            sum += e;
        }
        float inv = 1.0f / sum;
#pragma unroll
        for (int s = 0; s < 16; s++) attn[tid][s] *= inv;
    }
    __syncthreads();

    const int t = r;
    float o[8];
#pragma unroll
    for (int j = 0; j < 8; j++) o[j] = 0.f;
#pragma unroll
    for (int s = 0; s < 16; s++) {
        const float a = attn[t][s];
        const float* rv = rvs[s - t + 16];
#pragma unroll
        for (int j = 0; j < 8; j++)
            o[j] += a * (vs[s][c0 + j] + rv[c0 + j]);
    }

    // bf16 split store: [hi | lo]
    __nv_bfloat16 hb[8], lb[8];
#pragma unroll
    for (int j = 0; j < 8; j++) {
        hb[j] = __float2bfloat16(o[j]);
        lb[j] = __float2bfloat16(o[j] - __bfloat162float(hb[j]));
    }
    __nv_bfloat16* op = a_cat + ((size_t)hw * T_LEN + t) * KPHYS + h * DHEAD + c0;
    uint4 hp, lp;
    memcpy(&hp, hb, 16); memcpy(&lp, lb, 16);
    *(uint4*)(op)       = hp;
    *(uint4*)(op + 512) = lp;
}

// ---------------------------------------------------------------------------
extern "C" void kernel_launch(void* const* d_in, const int* in_sizes, int n_in,
                              void* d_out, int out_size)
{
    const float* x   = (const float*)d_in[0];
    const float* Wq  = (const float*)d_in[1];
    const float* Wk  = (const float*)d_in[2];
    const float* Wv  = (const float*)d_in[3];
    const float* Wo  = (const float*)d_in[4];
    const float* bo  = (const float*)d_in[5];
    const float* rk  = (const float*)d_in[6];
    const float* rv  = (const float*)d_in[7];
    float* out = (float*)d_out;

    float *qkv = nullptr;
    __nv_bfloat16 *xcat = nullptr, *acat = nullptr, *w1 = nullptr, *w2 = nullptr;
    cudaGetSymbolAddress((void**)&qkv, g_qkv);
    cudaGetSymbolAddress((void**)&xcat, g_xcat);
    cudaGetSymbolAddress((void**)&acat, g_acat);
    cudaGetSymbolAddress((void**)&w1, g_w1);
    cudaGetSymbolAddress((void**)&w2, g_w2);

    cudaFuncSetAttribute(mma_gemm, cudaFuncAttributeMaxDynamicSharedMemorySize,
                         SMEM_TOTAL);

    // conversions
    split_x<<<(MROWS * 128 + 255) / 256, 256>>>(x, xcat);
    split_w1<<<1536, 128>>>(Wq, Wk, Wv, w1);
    split_w2<<<512, 128>>>(Wo, w2);

    // QKV projection: [40960,1536] = x_cat @ w1^T (logical K=1536)
    mma_gemm<<<dim3(1536 / BN, MROWS / BM), 128, SMEM_TOTAL>>>(
        xcat, w1, nullptr, qkv, 1536);

    // attention
    attn_kernel<<<dim3(NHEAD, HW_N), 128>>>(qkv, rk, rv, acat);

    // output projection: [40960,512] = a_cat @ w2^T + bo
    mma_gemm<<<dim3(512 / BN, MROWS / BM), 128, SMEM_TOTAL>>>(
        acat, w2, bo, out, 512);
}

// round 11
// speedup vs baseline: 2.9837x; 1.0142x over previous
#include <cuda_runtime.h>
#include <cuda_bf16.h>
#include <cstdint>

// ----------------------------------------------------------------------------
// FreeTraj temporal attention. GEMMs via baseline-PTX bf16 mma.sync (HMMA),
// 3-term bf16 split: a*b ~= hiA*hiB + hiA*loB + loA*hiB  (logical K=1536).
// Physical storage dedup: A phys [hi|lo] (K=1024), logical segs {hi,hi,lo};
//                         B phys [hi|lo] (K=1024), logical segs {hi,lo,hi}.
// ----------------------------------------------------------------------------

#define HW_N   2560
#define T_LEN  16
#define NHEAD  8
#define DHEAD  64
#define MROWS  (HW_N * T_LEN)   // 40960
#define KPHYS  1024             // physical row stride (bf16 elements)
#define NKI    24               // logical K chunks of 64 (24*64 = 1536)

#define BM 128
#define BN 128
#define BK 64
#define STAGE_BYTES 32768        // A 16KB + B 16KB
#define SMEM_TOTAL (3 * STAGE_BYTES)

__device__ float         g_qkv[(size_t)MROWS * 1536];
__device__ __nv_bfloat16 g_xcat[(size_t)MROWS * KPHYS];
__device__ __nv_bfloat16 g_acat[(size_t)MROWS * KPHYS];
__device__ __nv_bfloat16 g_w1[(size_t)1536 * KPHYS];
__device__ __nv_bfloat16 g_w2[(size_t)512 * KPHYS];

// ------------------------------- helpers -----------------------------------
__device__ __forceinline__ uint32_t smem_u32(const void* p) {
    uint32_t a;
    asm("{ .reg .u64 t; cvta.to.shared.u64 t, %1; cvt.u32.u64 %0, t; }"
        : "=r"(a) : "l"(p));
    return a;
}
#define CP_ASYNC16(sa, gp) \
    asm volatile("cp.async.cg.shared.global [%0], [%1], 16;" \
                 :: "r"(sa), "l"(gp))
#define CP_COMMIT() asm volatile("cp.async.commit_group;" ::: "memory")

__device__ __forceinline__ void ldsm4(uint32_t* r, uint32_t addr) {
    asm volatile("ldmatrix.sync.aligned.m8n8.x4.shared.b16 {%0,%1,%2,%3}, [%4];"
                 : "=r"(r[0]), "=r"(r[1]), "=r"(r[2]), "=r"(r[3]) : "r"(addr));
}

// logical chunk -> physical bf16 offset within a row
__device__ __forceinline__ int ko_a(int c) {   // A segs: hi,hi,lo
    return ((c >> 3) == 2 ? 512 : 0) + (c & 7) * 64;
}
__device__ __forceinline__ int ko_b(int c) {   // B segs: hi,lo,hi
    return ((c >> 3) == 1 ? 512 : 0) + (c & 7) * 64;
}

// ---------------------------------------------------------------------------
// bf16 GEMM: C[M, Ntot] fp32 = A @ B^T (+bias), logical K=1536 over phys 1024.
// CTA 128x128, BK=64, 3-stage cp.async. 256 threads: 8 warps, 2m x 4n grid,
// warp tile 64x32. 2 CTAs/SM -> 16 resident warps.
// ---------------------------------------------------------------------------
__global__ __launch_bounds__(256, 2) void mma_gemm(
    const __nv_bfloat16* __restrict__ A,
    const __nv_bfloat16* __restrict__ B,
    const float* __restrict__ bias,
    float* __restrict__ C,
    int Ntot)
{
    extern __shared__ char smem[];
    const uint32_t sb = smem_u32(smem);
    const int tid = threadIdx.x;
    const int l = tid & 31, w = tid >> 5;
    const int wm = (w & 1) << 6;      // 0 / 64
    const int wn = (w >> 1) << 5;     // 0 / 32 / 64 / 96
    const size_t m0 = (size_t)blockIdx.y * BM;
    const size_t n0 = (size_t)blockIdx.x * BN;

    // cp.async mapping: 4 A chunks + 4 B chunks of 16B per thread per stage
    uint32_t stA[4], stB[4], oA[4], oB[4];
#pragma unroll
    for (int i = 0; i < 4; i++) {
        const int id = i * 256 + tid;
        const int row = id >> 3, kc = id & 7;
        const uint32_t so = (uint32_t)(row * 128 + ((kc ^ (row & 7)) << 4));
        stA[i] = so;
        stB[i] = so + 16384;
        oA[i] = (uint32_t)((m0 + row) * KPHYS + kc * 8);
        oB[i] = (uint32_t)((n0 + row) * KPHYS + kc * 8);
    }

#define LOAD_STAGE(s, c) do {                                               \
    const uint32_t _b = sb + (uint32_t)(s) * STAGE_BYTES;                   \
    const int _ka = ko_a(c), _kb = ko_b(c);                                 \
    _Pragma("unroll")                                                       \
    for (int _i = 0; _i < 4; _i++) CP_ASYNC16(_b + stA[_i], A + oA[_i] + _ka); \
    _Pragma("unroll")                                                       \
    for (int _i = 0; _i < 4; _i++) CP_ASYNC16(_b + stB[_i], B + oB[_i] + _kb); \
    CP_COMMIT();                                                            \
} while (0)

    LOAD_STAGE(0, 0);
    LOAD_STAGE(1, 1);

    // ldmatrix lane addressing
    const int arow = wm + (l & 15);
    const int kadd_a = (l >> 4) & 1;
    const int brow = wn + (l & 7) + ((l & 16) >> 1);
    const int kadd_b = (l >> 3) & 1;
    const int axor = arow & 7, bxor = brow & 7;

    float acc[4][4][4];
#pragma unroll
    for (int i = 0; i < 4; i++)
#pragma unroll
        for (int j = 0; j < 4; j++)
#pragma unroll
            for (int q = 0; q < 4; q++) acc[i][j][q] = 0.f;

    for (int c = 0; c < NKI; c++) {
        if (c < NKI - 1) asm volatile("cp.async.wait_group 1;" ::: "memory");
        else             asm volatile("cp.async.wait_group 0;" ::: "memory");
        __syncthreads();
        if (c + 2 < NKI) LOAD_STAGE((c + 2) % 3, c + 2);

        const uint32_t base = sb + (uint32_t)(c % 3) * STAGE_BYTES;
#pragma unroll
        for (int ks = 0; ks < 4; ks++) {
            const uint32_t kca = (uint32_t)((ks * 2 + kadd_a) ^ axor) << 4;
            const uint32_t kcb = (uint32_t)((ks * 2 + kadd_b) ^ bxor) << 4;
            uint32_t af[4][4], bf[2][4];
#pragma unroll
            for (int im = 0; im < 4; im++)
                ldsm4(af[im], base + (uint32_t)(arow + im * 16) * 128 + kca);
#pragma unroll
            for (int jn = 0; jn < 2; jn++)
                ldsm4(bf[jn], base + 16384 +
                              (uint32_t)(brow + jn * 16) * 128 + kcb);
#pragma unroll
            for (int im = 0; im < 4; im++)
#pragma unroll
                for (int j = 0; j < 4; j++) {
                    const uint32_t* bb = &bf[j >> 1][(j & 1) * 2];
                    asm volatile(
                        "mma.sync.aligned.m16n8k16.row.col.f32.bf16.bf16.f32 "
                        "{%0,%1,%2,%3}, {%4,%5,%6,%7}, {%8,%9}, {%0,%1,%2,%3};"
                        : "+f"(acc[im][j][0]), "+f"(acc[im][j][1]),
                          "+f"(acc[im][j][2]), "+f"(acc[im][j][3])
                        : "r"(af[im][0]), "r"(af[im][1]), "r"(af[im][2]),
                          "r"(af[im][3]), "r"(bb[0]), "r"(bb[1]));
                }
        }
    }

    // epilogue: direct stores (float2 per lane)
#pragma unroll
    for (int im = 0; im < 4; im++) {
        const size_t r_ = m0 + wm + im * 16 + (l >> 2);
#pragma unroll
        for (int j = 0; j < 4; j++) {
            const size_t c_ = n0 + wn + j * 8 + ((l & 3) << 1);
            float bx = 0.f, by = 0.f;
            if (bias) { bx = bias[c_]; by = bias[c_ + 1]; }
            float2 v0 = make_float2(acc[im][j][0] + bx, acc[im][j][1] + by);
            float2 v1 = make_float2(acc[im][j][2] + bx, acc[im][j][3] + by);
            *(float2*)&C[r_ * Ntot + c_] = v0;
            *(float2*)&C[(r_ + 8) * Ntot + c_] = v1;
        }
    }
#undef LOAD_STAGE
}

// ---------------------------------------------------------------------------
// Fused split conversions (physical [hi|lo], K=1024).
// blocks [0, NXB): x rows; [NXB, NXB+1536): w1 cols; [NXB+1536, +512): w2 cols.
// ---------------------------------------------------------------------------
#define NXB ((MROWS * 128 + 255) / 256)
__global__ void split_all(const float* __restrict__ x,
                          const float* __restrict__ Wq,
                          const float* __restrict__ Wk,
                          const float* __restrict__ Wv,
                          const float* __restrict__ Wo,
                          __nv_bfloat16* __restrict__ xcat,
                          __nv_bfloat16* __restrict__ w1,
                          __nv_bfloat16* __restrict__ w2)
{
    const int b = blockIdx.x;
    if (b < NXB) {
        const int idx = b * 256 + threadIdx.x;
        if (idx >= MROWS * 128) return;
        const int m = idx >> 7, k4 = idx & 127;
        float4 v = ((const float4*)x)[idx];
        __nv_bfloat16 h[4], l[4];
        float f[4] = {v.x, v.y, v.z, v.w};
#pragma unroll
        for (int i = 0; i < 4; i++) {
            h[i] = __float2bfloat16(f[i]);
            l[i] = __float2bfloat16(f[i] - __bfloat162float(h[i]));
        }
        __nv_bfloat16* d = xcat + (size_t)m * KPHYS + k4 * 4;
        uint2 hp, lp;
        memcpy(&hp, h, 8); memcpy(&lp, l, 8);
        *(uint2*)(d)       = hp;
        *(uint2*)(d + 512) = lp;
    } else if (b < NXB + 1536) {
        const int n = b - NXB;
        const float* W = (n < 512) ? Wq : ((n < 1024) ? Wk : Wv);
        const int nc = n & 511;
        for (int k = threadIdx.x; k < 512; k += 256) {
            const float v = W[(size_t)k * 512 + nc];
            __nv_bfloat16 h = __float2bfloat16(v);
            __nv_bfloat16 l = __float2bfloat16(v - __bfloat162float(h));
            w1[(size_t)n * KPHYS + k]       = h;
            w1[(size_t)n * KPHYS + 512 + k] = l;
        }
    } else {
        const int n = b - NXB - 1536;
        for (int k = threadIdx.x; k < 512; k += 256) {
            const float v = Wo[(size_t)k * 512 + n];
            __nv_bfloat16 h = __float2bfloat16(v);
            __nv_bfloat16 l = __float2bfloat16(v - __bfloat162float(h));
            w2[(size_t)n * KPHYS + k]       = h;
            w2[(size_t)n * KPHYS + 512 + k] = l;
        }
    }
}

// ---------------------------------------------------------------------------
// Attention: one block per (head-pair, hw); 256 threads (128 per head).
// Outputs bf16 split [hi|lo] (K=1024). smem stride 65 -> conflict-free.
// Trajectory box tables computed on HOST (exact Python double semantics).
// ---------------------------------------------------------------------------
struct TrajTab { int hs[16]; int ws[16]; int subh, subw; };

#define APAD 65
__global__ __launch_bounds__(256) void attn_kernel(
    const float* __restrict__ qkv,
    const float* __restrict__ rel_k,
    const float* __restrict__ rel_v,
    __nv_bfloat16* __restrict__ a_cat,
    TrajTab tt)
{
    const int h0 = blockIdx.x * 2;   // head pair base
    const int hw = blockIdx.y;
    const int tid = threadIdx.x;
    const int hh  = tid >> 7;        // 0/1: which head of the pair
    const int sub = tid & 127;

    __shared__ float qs[2][16][APAD];
    __shared__ float ks[2][16][APAD];
    __shared__ float vs[2][16][APAD];
    __shared__ float rks[33][APAD];
    __shared__ float rvs[33][APAD];
    __shared__ float sim[2][16][17];
    __shared__ float attn[2][16][17];

    const float* base = qkv + (size_t)hw * T_LEN * 1536 + (h0 + hh) * DHEAD;
    const int r  = sub >> 3;
    const int c0 = (sub & 7) * 8;

#pragma unroll
    for (int j = 0; j < 2; j++) {
        float4 a = *(const float4*)&base[(size_t)r * 1536 + c0 + 4 * j];
        float4 b = *(const float4*)&base[(size_t)r * 1536 + 512 + c0 + 4 * j];
        float4 c = *(const float4*)&base[(size_t)r * 1536 + 1024 + c0 + 4 * j];
        qs[hh][r][c0 + 4 * j + 0] = a.x; qs[hh][r][c0 + 4 * j + 1] = a.y;
        qs[hh][r][c0 + 4 * j + 2] = a.z; qs[hh][r][c0 + 4 * j + 3] = a.w;
        ks[hh][r][c0 + 4 * j + 0] = b.x; ks[hh][r][c0 + 4 * j + 1] = b.y;
        ks[hh][r][c0 + 4 * j + 2] = b.z; ks[hh][r][c0 + 4 * j + 3] = b.w;
        vs[hh][r][c0 + 4 * j + 0] = c.x; vs[hh][r][c0 + 4 * j + 1] = c.y;
        vs[hh][r][c0 + 4 * j + 2] = c.z; vs[hh][r][c0 + 4 * j + 3] = c.w;
    }
    for (int i = tid; i < 33 * 16; i += 256) {
        const int row = i >> 4, q4 = (i & 15) * 4;
        float4 a = ((const float4*)rel_k)[i];
        float4 b = ((const float4*)rel_v)[i];
        rks[row][q4 + 0] = a.x; rks[row][q4 + 1] = a.y;
        rks[row][q4 + 2] = a.z; rks[row][q4 + 3] = a.w;
        rvs[row][q4 + 0] = b.x; rvs[row][q4 + 1] = b.y;
        rvs[row][q4 + 2] = b.z; rvs[row][q4 + 3] = b.w;
    }

    // freetraj fg bitmask from host-computed tables (pure int ops)
    const int y  = hw / 40;
    const int xx = hw % 40;
    unsigned fgm = 0;
#pragma unroll
    for (int i = 0; i < 16; i++) {
        if (y >= tt.hs[i] && y < tt.hs[i] + tt.subh &&
            xx >= tt.ws[i] && xx < tt.ws[i] + tt.subw)
            fgm |= (1u << i);
    }
    __syncthreads();

#pragma unroll
    for (int pp = 0; pp < 2; pp++) {
        const int p = sub + pp * 128;
        const int t = p >> 4, s = p & 15;
        const float* rk = rks[s - t + 16];
        float acc = 0.f;
#pragma unroll
        for (int d = 0; d < 64; d++)
            acc += qs[hh][t][d] * (ks[hh][s][d] + rk[d]);
        const float m = (((fgm >> t) & 1u) == ((fgm >> s) & 1u)) ? 1.0f : 0.01f;
        sim[hh][t][s] = acc * 0.125f * m;
    }
    __syncthreads();

    if (sub < 16) {
        float mx = -1e30f;
#pragma unroll
        for (int s = 0; s < 16; s++) mx = fmaxf(mx, sim[hh][sub][s]);
        float sum = 0.f;
#pragma unroll
        for (int s = 0; s < 16; s++) {
            float e = expf(sim[hh][sub][s] - mx);
            attn[hh][sub][s] = e;
            sum += e;
        }
        float inv = 1.0f / sum;
#pragma unroll
        for (int s = 0; s < 16; s++) attn[hh][sub][s] *= inv;
    }
    __syncthreads();

    const int t = r;
    float o[8];
#pragma unroll
    for (int j = 0; j < 8; j++) o[j] = 0.f;
#pragma unroll
    for (int s = 0; s < 16; s++) {
        const float a = attn[hh][t][s];
        const float* rv = rvs[s - t + 16];
#pragma unroll
        for (int j = 0; j < 8; j++)
            o[j] += a * (vs[hh][s][c0 + j] + rv[c0 + j]);
    }

    // bf16 split store: [hi | lo]
    __nv_bfloat16 hb[8], lb[8];
#pragma unroll
    for (int j = 0; j < 8; j++) {
        hb[j] = __float2bfloat16(o[j]);
        lb[j] = __float2bfloat16(o[j] - __bfloat162float(hb[j]));
    }
    __nv_bfloat16* op = a_cat + ((size_t)hw * T_LEN + t) * KPHYS +
                        (h0 + hh) * DHEAD + c0;
    uint4 hp, lp;
    memcpy(&hp, hb, 16); memcpy(&lp, lb, 16);
    *(uint4*)(op)       = hp;
    *(uint4*)(op + 512) = lp;
}

// ---------------------------------------------------------------------------
extern "C" void kernel_launch(void* const* d_in, const int* in_sizes, int n_in,
                              void* d_out, int out_size)
{
    const float* x   = (const float*)d_in[0];
    const float* Wq  = (const float*)d_in[1];
    const float* Wk  = (const float*)d_in[2];
    const float* Wv  = (const float*)d_in[3];
    const float* Wo  = (const float*)d_in[4];
    const float* bo  = (const float*)d_in[5];
    const float* rk  = (const float*)d_in[6];
    const float* rv  = (const float*)d_in[7];
    float* out = (float*)d_out;

    float *qkv = nullptr;
    __nv_bfloat16 *xcat = nullptr, *acat = nullptr, *w1 = nullptr, *w2 = nullptr;
    cudaGetSymbolAddress((void**)&qkv, g_qkv);
    cudaGetSymbolAddress((void**)&xcat, g_xcat);
    cudaGetSymbolAddress((void**)&acat, g_acat);
    cudaGetSymbolAddress((void**)&w1, g_w1);
    cudaGetSymbolAddress((void**)&w2, g_w2);

    cudaFuncSetAttribute(mma_gemm, cudaFuncAttributeMaxDynamicSharedMemorySize,
                         SMEM_TOTAL);

    // host-side trajectory tables (exact Python double semantics)
    TrajTab tt;
    tt.subh = (int)((0.35 - 0.10) * 64.0);   // 15
    tt.subw = (int)((0.35 - 0.10) * 40.0);   // 9
    for (int i = 0; i < 16; i++) {
        double rr = (double)i / 15.0;
        double ph = 0.10 + rr * (0.60 - 0.10);
        double pw = 0.10 + rr * (0.60 - 0.10);
        tt.hs[i] = (int)(ph * 64.0);
        tt.ws[i] = (int)(pw * 40.0);
    }

    // conversions (one fused launch)
    split_all<<<NXB + 1536 + 512, 256>>>(x, Wq, Wk, Wv, Wo, xcat, w1, w2);

    // QKV projection: [40960,1536] = x_cat @ w1^T (logical K=1536)
    mma_gemm<<<dim3(1536 / BN, MROWS / BM), 256, SMEM_TOTAL>>>(
        xcat, w1, nullptr, qkv, 1536);

    // attention (2 heads per block)
    attn_kernel<<<dim3(NHEAD / 2, HW_N), 256>>>(qkv, rk, rv, acat, tt);

    // output projection: [40960,512] = a_cat @ w2^T + bo
    mma_gemm<<<dim3(512 / BN, MROWS / BM), 256, SMEM_TOTAL>>>(
        acat, w2, bo, out, 512);
}

// round 13
// speedup vs baseline: 3.4551x; 1.1580x over previous
#include <cuda_runtime.h>
#include <cuda_bf16.h>
#include <cstdint>

// ----------------------------------------------------------------------------
// FreeTraj temporal attention, tf32 single-pass GEMMs (mma.sync.m16n8k8.tf32).
// All GEMM operands are fp32 tensors whose mantissas were pre-rounded to tf32
// (cvt.rna.tf32.f32), so the GEMM kernel loads raw 32-bit words; no in-loop cvt.
// Pipeline:
//   prep    : x -> xt (tf32-rounded), Wq|Wk|Wv^T -> w1t, Wo^T -> w2t
//   mma_gemm: qkv fp32 [40960,1536] = xt @ w1t^T        (K=512)
//   attn    : 16x16 attention per (hw,2 heads) -> att (tf32-rounded fp32)
//   mma_gemm: out fp32 [40960,512] = att @ w2t^T + bo   (K=512)
// ----------------------------------------------------------------------------

#define HW_N   2560
#define T_LEN  16
#define NHEAD  8
#define DHEAD  64
#define MROWS  (HW_N * T_LEN)   // 40960
#define KDIM   512

#define BM 128
#define BN 128
#define BKF 32                   // K per chunk (floats)
#define NCH (KDIM / BKF)         // 16
#define STAGE_BYTES 32768        // A 16KB + B 16KB (128 rows x 128B each)
#define SMEM_TOTAL (3 * STAGE_BYTES)

__device__ float g_qkv[(size_t)MROWS * 1536];
__device__ float g_xt [(size_t)MROWS * KDIM];
__device__ float g_att[(size_t)MROWS * KDIM];
__device__ float g_w1t[(size_t)1536 * KDIM];
__device__ float g_w2t[(size_t)512 * KDIM];

// ------------------------------- helpers -----------------------------------
__device__ __forceinline__ uint32_t smem_u32(const void* p) {
    uint32_t a;
    asm("{ .reg .u64 t; cvta.to.shared.u64 t, %1; cvt.u32.u64 %0, t; }"
        : "=r"(a) : "l"(p));
    return a;
}
#define CP_ASYNC16(sa, gp) \
    asm volatile("cp.async.cg.shared.global [%0], [%1], 16;" \
                 :: "r"(sa), "l"(gp))
#define CP_COMMIT() asm volatile("cp.async.commit_group;" ::: "memory")

__device__ __forceinline__ uint32_t tf32r(float f) {
    uint32_t u;
    asm("cvt.rna.tf32.f32 %0, %1;" : "=r"(u) : "f"(f));
    return u;
}
__device__ __forceinline__ uint32_t lds32(const char* p) {
    return *(const uint32_t*)p;
}

// ---------------------------------------------------------------------------
// tf32 GEMM: C[M, Ntot] fp32 = A[M,512] @ B[Ntot,512]^T (+bias).
// A, B fp32 row-major (values already tf32-rounded).
// CTA 128x128, BK=32 floats, 3-stage cp.async. 256 threads: 8 warps,
// 2m x 4n grid, warp tile 64x32 (m16n8k8: 4m x 4n x 4k steps).
// smem rows 128B (32 floats), XOR-swizzled 16B chunks.
// ---------------------------------------------------------------------------
__global__ __launch_bounds__(256, 2) void mma_gemm(
    const float* __restrict__ A,
    const float* __restrict__ B,
    const float* __restrict__ bias,
    float* __restrict__ C,
    int Ntot)
{
    extern __shared__ char smem[];
    const uint32_t sb = smem_u32(smem);
    const int tid = threadIdx.x;
    const int l = tid & 31, w = tid >> 5;
    const int wm = (w & 1) << 6;      // 0 / 64
    const int wn = (w >> 1) << 5;     // 0 / 32 / 64 / 96
    const size_t m0 = (size_t)blockIdx.y * BM;
    const size_t n0 = (size_t)blockIdx.x * BN;

    // cp.async mapping: 4 A chunks + 4 B chunks of 16B per thread per stage
    uint32_t stA[4], stB[4], oA[4], oB[4];
#pragma unroll
    for (int i = 0; i < 4; i++) {
        const int id = i * 256 + tid;
        const int row = id >> 3, kc = id & 7;      // 128 rows x 8 chunks
        const uint32_t so = (uint32_t)(row * 128 + ((kc ^ (row & 7)) << 4));
        stA[i] = so;
        stB[i] = so + 16384;
        oA[i] = (uint32_t)((m0 + row) * KDIM + kc * 4);
        oB[i] = (uint32_t)((n0 + row) * KDIM + kc * 4);
    }

#define LOAD_STAGE(s, c) do {                                               \
    const uint32_t _b = sb + (uint32_t)(s) * STAGE_BYTES;                   \
    const uint32_t _ko = (uint32_t)(c) * BKF;                               \
    _Pragma("unroll")                                                       \
    for (int _i = 0; _i < 4; _i++) CP_ASYNC16(_b + stA[_i], A + oA[_i] + _ko); \
    _Pragma("unroll")                                                       \
    for (int _i = 0; _i < 4; _i++) CP_ASYNC16(_b + stB[_i], B + oB[_i] + _ko); \
    CP_COMMIT();                                                            \
} while (0)

    LOAD_STAGE(0, 0);
    LOAD_STAGE(1, 1);

    // fragment lane addressing (m16n8k8 tf32)
    const int g = l >> 2;            // group 0..7
    const int t4 = l & 3;            // 0..3 (k low bits / col pair)
    float acc[4][4][4];
#pragma unroll
    for (int i = 0; i < 4; i++)
#pragma unroll
        for (int j = 0; j < 4; j++)
#pragma unroll
            for (int q = 0; q < 4; q++) acc[i][j][q] = 0.f;

    for (int c = 0; c < NCH; c++) {
        if (c < NCH - 1) asm volatile("cp.async.wait_group 1;" ::: "memory");
        else             asm volatile("cp.async.wait_group 0;" ::: "memory");
        __syncthreads();
        if (c + 2 < NCH) LOAD_STAGE((c + 2) % 3, c + 2);

        const char* base = smem + (size_t)(c % 3) * STAGE_BYTES;
        const char* bbase = base + 16384;
#pragma unroll
        for (int ks = 0; ks < 4; ks++) {
            // A fragments: rows wm+g+im*16 (+8), cols ks*8+t4 (+4)
            uint32_t af[4][4];
#pragma unroll
            for (int im = 0; im < 4; im++) {
                const int r0 = wm + g + im * 16;
                const int x0 = (2 * ks) ^ (r0 & 7);      // chunk for col ks*8+t4
                const int x1 = (2 * ks + 1) ^ (r0 & 7);  // chunk for col +4
                const char* p0 = base + r0 * 128;
                const char* p1 = base + (r0 + 8) * 128;  // (r0+8)&7 == r0&7
                af[im][0] = lds32(p0 + (x0 << 4) + t4 * 4);
                af[im][1] = lds32(p1 + (x0 << 4) + t4 * 4);
                af[im][2] = lds32(p0 + (x1 << 4) + t4 * 4);
                af[im][3] = lds32(p1 + (x1 << 4) + t4 * 4);
            }
            // B fragments: rows wn+jn*8+g, cols ks*8+t4 (+4)
            uint32_t bf[4][2];
#pragma unroll
            for (int jn = 0; jn < 4; jn++) {
                const int rB = wn + jn * 8 + g;
                const int x0 = (2 * ks) ^ (rB & 7);
                const int x1 = (2 * ks + 1) ^ (rB & 7);
                const char* pB = bbase + rB * 128;
                bf[jn][0] = lds32(pB + (x0 << 4) + t4 * 4);
                bf[jn][1] = lds32(pB + (x1 << 4) + t4 * 4);
            }
#pragma unroll
            for (int im = 0; im < 4; im++)
#pragma unroll
                for (int jn = 0; jn < 4; jn++)
                    asm volatile(
                        "mma.sync.aligned.m16n8k8.row.col.f32.tf32.tf32.f32 "
                        "{%0,%1,%2,%3}, {%4,%5,%6,%7}, {%8,%9}, {%0,%1,%2,%3};"
                        : "+f"(acc[im][jn][0]), "+f"(acc[im][jn][1]),
                          "+f"(acc[im][jn][2]), "+f"(acc[im][jn][3])
                        : "r"(af[im][0]), "r"(af[im][1]), "r"(af[im][2]),
                          "r"(af[im][3]), "r"(bf[jn][0]), "r"(bf[jn][1]));
        }
    }

    // epilogue: direct stores (float2 per lane)
#pragma unroll
    for (int im = 0; im < 4; im++) {
        const size_t r_ = m0 + wm + im * 16 + g;
#pragma unroll
        for (int jn = 0; jn < 4; jn++) {
            const size_t c_ = n0 + wn + jn * 8 + (t4 << 1);
            float bx = 0.f, by = 0.f;
            if (bias) { bx = bias[c_]; by = bias[c_ + 1]; }
            float2 v0 = make_float2(acc[im][jn][0] + bx, acc[im][jn][1] + by);
            float2 v1 = make_float2(acc[im][jn][2] + bx, acc[im][jn][3] + by);
            *(float2*)&C[r_ * Ntot + c_] = v0;
            *(float2*)&C[(r_ + 8) * Ntot + c_] = v1;
        }
    }
#undef LOAD_STAGE
}

// ---------------------------------------------------------------------------
// Prep: tf32-round x; transpose+round weights.
// blocks [0, NXB): x float4s; [NXB, NXB+1536): w1t cols; [+512): w2t cols.
// ---------------------------------------------------------------------------
#define NXB ((MROWS * 128 + 255) / 256)
__global__ void prep_all(const float* __restrict__ x,
                         const float* __restrict__ Wq,
                         const float* __restrict__ Wk,
                         const float* __restrict__ Wv,
                         const float* __restrict__ Wo,
                         float* __restrict__ xt,
                         float* __restrict__ w1t,
                         float* __restrict__ w2t)
{
    const int b = blockIdx.x;
    if (b < NXB) {
        const int idx = b * 256 + threadIdx.x;   // over MROWS*512/4
        if (idx >= MROWS * 128) return;
        float4 v = ((const float4*)x)[idx];
        uint4 r;
        r.x = tf32r(v.x); r.y = tf32r(v.y); r.z = tf32r(v.z); r.w = tf32r(v.w);
        ((uint4*)xt)[idx] = r;
    } else if (b < NXB + 1536) {
        const int n = b - NXB;
        const float* W = (n < 512) ? Wq : ((n < 1024) ? Wk : Wv);
        const int nc = n & 511;
        uint32_t* d = (uint32_t*)(w1t + (size_t)n * KDIM);
        for (int k = threadIdx.x; k < 512; k += 256)
            d[k] = tf32r(W[(size_t)k * 512 + nc]);
    } else {
        const int n = b - NXB - 1536;
        uint32_t* d = (uint32_t*)(w2t + (size_t)n * KDIM);
        for (int k = threadIdx.x; k < 512; k += 256)
            d[k] = tf32r(Wo[(size_t)k * 512 + n]);
    }
}

// ---------------------------------------------------------------------------
// Attention: one block per (head-pair, hw); 256 threads (128 per head).
// Outputs tf32-rounded fp32 [40960,512]. smem stride 65 -> conflict-free.
// ---------------------------------------------------------------------------
struct TrajTab { int hs[16]; int ws[16]; int subh, subw; };

#define APAD 65
__global__ __launch_bounds__(256) void attn_kernel(
    const float* __restrict__ qkv,
    const float* __restrict__ rel_k,
    const float* __restrict__ rel_v,
    float* __restrict__ att,
    TrajTab tt)
{
    const int h0 = blockIdx.x * 2;
    const int hw = blockIdx.y;
    const int tid = threadIdx.x;
    const int hh  = tid >> 7;
    const int sub = tid & 127;

    __shared__ float qs[2][16][APAD];
    __shared__ float ks[2][16][APAD];
    __shared__ float vs[2][16][APAD];
    __shared__ float rks[33][APAD];
    __shared__ float rvs[33][APAD];
    __shared__ float sim[2][16][17];
    __shared__ float attnw[2][16][17];

    const float* base = qkv + (size_t)hw * T_LEN * 1536 + (h0 + hh) * DHEAD;
    const int r  = sub >> 3;
    const int c0 = (sub & 7) * 8;

#pragma unroll
    for (int j = 0; j < 2; j++) {
        float4 a = *(const float4*)&base[(size_t)r * 1536 + c0 + 4 * j];
        float4 b = *(const float4*)&base[(size_t)r * 1536 + 512 + c0 + 4 * j];
        float4 c = *(const float4*)&base[(size_t)r * 1536 + 1024 + c0 + 4 * j];
        qs[hh][r][c0 + 4 * j + 0] = a.x; qs[hh][r][c0 + 4 * j + 1] = a.y;
        qs[hh][r][c0 + 4 * j + 2] = a.z; qs[hh][r][c0 + 4 * j + 3] = a.w;
        ks[hh][r][c0 + 4 * j + 0] = b.x; ks[hh][r][c0 + 4 * j + 1] = b.y;
        ks[hh][r][c0 + 4 * j + 2] = b.z; ks[hh][r][c0 + 4 * j + 3] = b.w;
        vs[hh][r][c0 + 4 * j + 0] = c.x; vs[hh][r][c0 + 4 * j + 1] = c.y;
        vs[hh][r][c0 + 4 * j + 2] = c.z; vs[hh][r][c0 + 4 * j + 3] = c.w;
    }
    for (int i = tid; i < 33 * 16; i += 256) {
        const int row = i >> 4, q4 = (i & 15) * 4;
        float4 a = ((const float4*)rel_k)[i];
        float4 b = ((const float4*)rel_v)[i];
        rks[row][q4 + 0] = a.x; rks[row][q4 + 1] = a.y;
        rks[row][q4 + 2] = a.z; rks[row][q4 + 3] = a.w;
        rvs[row][q4 + 0] = b.x; rvs[row][q4 + 1] = b.y;
        rvs[row][q4 + 2] = b.z; rvs[row][q4 + 3] = b.w;
    }

    // freetraj fg bitmask from host-computed tables
    const int y  = hw / 40;
    const int xx = hw % 40;
    unsigned fgm = 0;
#pragma unroll
    for (int i = 0; i < 16; i++) {
        if (y >= tt.hs[i] && y < tt.hs[i] + tt.subh &&
            xx >= tt.ws[i] && xx < tt.ws[i] + tt.subw)
            fgm |= (1u << i);
    }
    __syncthreads();

#pragma unroll
    for (int pp = 0; pp < 2; pp++) {
        const int p = sub + pp * 128;
        const int t = p >> 4, s = p & 15;
        const float* rk = rks[s - t + 16];
        float acc = 0.f;
#pragma unroll
        for (int d = 0; d < 64; d++)
            acc += qs[hh][t][d] * (ks[hh][s][d] + rk[d]);
        const float m = (((fgm >> t) & 1u) == ((fgm >> s) & 1u)) ? 1.0f : 0.01f;
        sim[hh][t][s] = acc * 0.125f * m;
    }
    __syncthreads();

    if (sub < 16) {
        float mx = -1e30f;
#pragma unroll
        for (int s = 0; s < 16; s++) mx = fmaxf(mx, sim[hh][sub][s]);
        float sum = 0.f;
#pragma unroll
        for (int s = 0; s < 16; s++) {
            float e = expf(sim[hh][sub][s] - mx);
            attnw[hh][sub][s] = e;
            sum += e;
        }
        float inv = 1.0f / sum;
#pragma unroll
        for (int s = 0; s < 16; s++) attnw[hh][sub][s] *= inv;
    }
    __syncthreads();

    const int t = r;
    float o[8];
#pragma unroll
    for (int j = 0; j < 8; j++) o[j] = 0.f;
#pragma unroll
    for (int s = 0; s < 16; s++) {
        const float a = attnw[hh][t][s];
        const float* rv = rvs[s - t + 16];
#pragma unroll
        for (int j = 0; j < 8; j++)
            o[j] += a * (vs[hh][s][c0 + j] + rv[c0 + j]);
    }

    // tf32-rounded fp32 store (GEMM2 consumes raw bits)
    uint4 p0, p1;
    p0.x = tf32r(o[0]); p0.y = tf32r(o[1]); p0.z = tf32r(o[2]); p0.w = tf32r(o[3]);
    p1.x = tf32r(o[4]); p1.y = tf32r(o[5]); p1.z = tf32r(o[6]); p1.w = tf32r(o[7]);
    uint32_t* op = (uint32_t*)(att + ((size_t)hw * T_LEN + t) * KDIM +
                               (h0 + hh) * DHEAD + c0);
    *(uint4*)(op)     = p0;
    *(uint4*)(op + 4) = p1;
}

// ---------------------------------------------------------------------------
extern "C" void kernel_launch(void* const* d_in, const int* in_sizes, int n_in,
                              void* d_out, int out_size)
{
    const float* x   = (const float*)d_in[0];
    const float* Wq  = (const float*)d_in[1];
    const float* Wk  = (const float*)d_in[2];
    const float* Wv  = (const float*)d_in[3];
    const float* Wo  = (const float*)d_in[4];
    const float* bo  = (const float*)d_in[5];
    const float* rk  = (const float*)d_in[6];
    const float* rv  = (const float*)d_in[7];
    float* out = (float*)d_out;

    float *qkv = nullptr, *xt = nullptr, *att = nullptr, *w1t = nullptr, *w2t = nullptr;
    cudaGetSymbolAddress((void**)&qkv, g_qkv);
    cudaGetSymbolAddress((void**)&xt,  g_xt);
    cudaGetSymbolAddress((void**)&att, g_att);
    cudaGetSymbolAddress((void**)&w1t, g_w1t);
    cudaGetSymbolAddress((void**)&w2t, g_w2t);

    cudaFuncSetAttribute(mma_gemm, cudaFuncAttributeMaxDynamicSharedMemorySize,
                         SMEM_TOTAL);

    // host-side trajectory tables (exact Python double semantics)
    TrajTab tt;
    tt.subh = (int)((0.35 - 0.10) * 64.0);   // 15
    tt.subw = (int)((0.35 - 0.10) * 40.0);   // 9
    for (int i = 0; i < 16; i++) {
        double rr = (double)i / 15.0;
        double ph = 0.10 + rr * (0.60 - 0.10);
        double pw = 0.10 + rr * (0.60 - 0.10);
        tt.hs[i] = (int)(ph * 64.0);
        tt.ws[i] = (int)(pw * 40.0);
    }

    // prep: tf32 rounding + weight transposes (one launch)
    prep_all<<<NXB + 1536 + 512, 256>>>(x, Wq, Wk, Wv, Wo, xt, w1t, w2t);

    // QKV projection: [40960,1536] = xt @ w1t^T
    mma_gemm<<<dim3(1536 / BN, MROWS / BM), 256, SMEM_TOTAL>>>(
        xt, w1t, nullptr, qkv, 1536);

    // attention (2 heads per block)
    attn_kernel<<<dim3(NHEAD / 2, HW_N), 256>>>(qkv, rk, rv, att, tt);

    // output projection: [40960,512] = att @ w2t^T + bo
    mma_gemm<<<dim3(512 / BN, MROWS / BM), 256, SMEM_TOTAL>>>(
        att, w2t, bo, out, 512);
}

// round 16
// speedup vs baseline: 3.6121x; 1.0454x over previous
#include <cuda_runtime.h>
#include <cuda_bf16.h>
#include <cstdint>

// ----------------------------------------------------------------------------
// FreeTraj temporal attention, tf32 single-pass GEMMs (mma.sync.m16n8k8.tf32).
// Fragments loaded via ldmatrix.b16 (tf32 m16n8k8 frag == bf16 m16n8k16 frag
// viewed as 32-bit words). Operands pre-rounded to tf32 (cvt.rna).
// Pipeline:
//   prep    : x -> xt (tf32-rounded), Wq|Wk|Wv^T -> w1t, Wo^T -> w2t
//   mma_gemm: qkv fp32 [40960,1536] = xt @ w1t^T        (K=512)
//   attn    : 16x16 attention per (hw,2 heads) -> att (tf32-rounded fp32)
//   mma_gemm: out fp32 [40960,512] = att @ w2t^T + bo   (K=512)
// ----------------------------------------------------------------------------

#define HW_N   2560
#define T_LEN  16
#define NHEAD  8
#define DHEAD  64
#define MROWS  (HW_N * T_LEN)   // 40960
#define KDIM   512

#define BM 128
#define BN 128
#define BKF 32                   // K per chunk (floats)
#define NCH (KDIM / BKF)         // 16
#define STAGE_BYTES 32768        // A 16KB + B 16KB (128 rows x 128B each)
#define SMEM_TOTAL (3 * STAGE_BYTES)

__device__ float g_qkv[(size_t)MROWS * 1536];
__device__ float g_xt [(size_t)MROWS * KDIM];
__device__ float g_att[(size_t)MROWS * KDIM];
__device__ float g_w1t[(size_t)1536 * KDIM];
__device__ float g_w2t[(size_t)512 * KDIM];

// ------------------------------- helpers -----------------------------------
__device__ __forceinline__ uint32_t smem_u32(const void* p) {
    uint32_t a;
    asm("{ .reg .u64 t; cvta.to.shared.u64 t, %1; cvt.u32.u64 %0, t; }"
        : "=r"(a) : "l"(p));
    return a;
}
#define CP_ASYNC16(sa, gp) \
    asm volatile("cp.async.cg.shared.global [%0], [%1], 16;" \
                 :: "r"(sa), "l"(gp))
#define CP_COMMIT() asm volatile("cp.async.commit_group;" ::: "memory")

__device__ __forceinline__ void ldsm4(uint32_t* r, uint32_t addr) {
    asm volatile("ldmatrix.sync.aligned.m8n8.x4.shared.b16 {%0,%1,%2,%3}, [%4];"
                 : "=r"(r[0]), "=r"(r[1]), "=r"(r[2]), "=r"(r[3]) : "r"(addr));
}
__device__ __forceinline__ uint32_t tf32r(float f) {
    uint32_t u;
    asm("cvt.rna.tf32.f32 %0, %1;" : "=r"(u) : "f"(f));
    return u;
}

// ---------------------------------------------------------------------------
// tf32 GEMM: C[M, Ntot] fp32 = A[M,512] @ B[Ntot,512]^T (+bias).
// CTA 128x128, BK=32 floats, 3-stage cp.async. 256 threads: 8 warps,
// 2m x 4n grid, warp tile 64x32. Fragments via ldmatrix.
// smem rows 128B (32 floats), XOR-swizzled 16B chunks.
// ---------------------------------------------------------------------------
__global__ __launch_bounds__(256, 2) void mma_gemm(
    const float* __restrict__ A,
    const float* __restrict__ B,
    const float* __restrict__ bias,
    float* __restrict__ C,
    int Ntot)
{
    extern __shared__ char smem[];
    const uint32_t sb = smem_u32(smem);
    const int tid = threadIdx.x;
    const int l = tid & 31, w = tid >> 5;
    const int wm = (w & 1) << 6;      // 0 / 64
    const int wn = (w >> 1) << 5;     // 0 / 32 / 64 / 96
    const size_t m0 = (size_t)blockIdx.y * BM;
    const size_t n0 = (size_t)blockIdx.x * BN;

    // cp.async mapping: 4 A chunks + 4 B chunks of 16B per thread per stage
    uint32_t stA[4], stB[4], oA[4], oB[4];
#pragma unroll
    for (int i = 0; i < 4; i++) {
        const int id = i * 256 + tid;
        const int row = id >> 3, kc = id & 7;      // 128 rows x 8 chunks
        const uint32_t so = (uint32_t)(row * 128 + ((kc ^ (row & 7)) << 4));
        stA[i] = so;
        stB[i] = so + 16384;
        oA[i] = (uint32_t)((m0 + row) * KDIM + kc * 4);
        oB[i] = (uint32_t)((n0 + row) * KDIM + kc * 4);
    }

#define LOAD_STAGE(s, c) do {                                               \
    const uint32_t _b = sb + (uint32_t)(s) * STAGE_BYTES;                   \
    const uint32_t _ko = (uint32_t)(c) * BKF;                               \
    _Pragma("unroll")                                                       \
    for (int _i = 0; _i < 4; _i++) CP_ASYNC16(_b + stA[_i], A + oA[_i] + _ko); \
    _Pragma("unroll")                                                       \
    for (int _i = 0; _i < 4; _i++) CP_ASYNC16(_b + stB[_i], B + oB[_i] + _ko); \
    CP_COMMIT();                                                            \
} while (0)

    LOAD_STAGE(0, 0);
    LOAD_STAGE(1, 1);

    // ldmatrix lane addressing (same pattern as validated bf16 kernel)
    const int arow = wm + (l & 15);              // A rows 0-15 of warp tile
    const int kadd_a = (l >> 4) & 1;             // chunk low bit
    const int brow = wn + (l & 7) + ((l & 16) >> 1);  // B: 0-7 / +8
    const int kadd_b = (l >> 3) & 1;
    const int axor = arow & 7, bxor = brow & 7;
    const int g = l >> 2, t4 = l & 3;            // epilogue lane coords

    float acc[4][4][4];
#pragma unroll
    for (int i = 0; i < 4; i++)
#pragma unroll
        for (int j = 0; j < 4; j++)
#pragma unroll
            for (int q = 0; q < 4; q++) acc[i][j][q] = 0.f;

    for (int c = 0; c < NCH; c++) {
        if (c < NCH - 1) asm volatile("cp.async.wait_group 1;" ::: "memory");
        else             asm volatile("cp.async.wait_group 0;" ::: "memory");
        __syncthreads();
        if (c + 2 < NCH) LOAD_STAGE((c + 2) % 3, c + 2);

        const uint32_t base  = sb + (uint32_t)(c % 3) * STAGE_BYTES;
        const uint32_t bbase = base + 16384;
#pragma unroll
        for (int ks = 0; ks < 4; ks++) {
            const uint32_t kca = (uint32_t)((2 * ks + kadd_a) ^ axor) << 4;
            const uint32_t kcb = (uint32_t)((2 * ks + kadd_b) ^ bxor) << 4;
            // A: 4 tiles of 16 rows; regs (as u32): (g,t4),(g+8,t4),(g,t4+4),(g+8,t4+4)
            uint32_t af[4][4];
#pragma unroll
            for (int im = 0; im < 4; im++)
                ldsm4(af[im], base + (uint32_t)(arow + im * 16) * 128 + kca);
            // B: 2 x 16 n-rows; regs: jn0{b0,b1}, jn1{b0,b1}
            uint32_t bfr[2][4];
#pragma unroll
            for (int jh = 0; jh < 2; jh++)
                ldsm4(bfr[jh], bbase + (uint32_t)(brow + jh * 16) * 128 + kcb);
#pragma unroll
            for (int im = 0; im < 4; im++)
#pragma unroll
                for (int jn = 0; jn < 4; jn++) {
                    const uint32_t* bb = &bfr[jn >> 1][(jn & 1) * 2];
                    asm volatile(
                        "mma.sync.aligned.m16n8k8.row.col.f32.tf32.tf32.f32 "
                        "{%0,%1,%2,%3}, {%4,%5,%6,%7}, {%8,%9}, {%0,%1,%2,%3};"
                        : "+f"(acc[im][jn][0]), "+f"(acc[im][jn][1]),
                          "+f"(acc[im][jn][2]), "+f"(acc[im][jn][3])
                        : "r"(af[im][0]), "r"(af[im][1]), "r"(af[im][2]),
                          "r"(af[im][3]), "r"(bb[0]), "r"(bb[1]));
                }
        }
    }

    // epilogue: direct stores (float2 per lane)
#pragma unroll
    for (int im = 0; im < 4; im++) {
        const size_t r_ = m0 + wm + im * 16 + g;
#pragma unroll
        for (int jn = 0; jn < 4; jn++) {
            const size_t c_ = n0 + wn + jn * 8 + (t4 << 1);
            float bx = 0.f, by = 0.f;
            if (bias) { bx = bias[c_]; by = bias[c_ + 1]; }
            float2 v0 = make_float2(acc[im][jn][0] + bx, acc[im][jn][1] + by);
            float2 v1 = make_float2(acc[im][jn][2] + bx, acc[im][jn][3] + by);
            *(float2*)&C[r_ * Ntot + c_] = v0;
            *(float2*)&C[(r_ + 8) * Ntot + c_] = v1;
        }
    }
#undef LOAD_STAGE
}

// ---------------------------------------------------------------------------
// Prep: tf32-round x; transpose+round weights.
// ---------------------------------------------------------------------------
#define NXB ((MROWS * 128 + 255) / 256)
__global__ void prep_all(const float* __restrict__ x,
                         const float* __restrict__ Wq,
                         const float* __restrict__ Wk,
                         const float* __restrict__ Wv,
                         const float* __restrict__ Wo,
                         float* __restrict__ xt,
                         float* __restrict__ w1t,
                         float* __restrict__ w2t)
{
    const int b = blockIdx.x;
    if (b < NXB) {
        const int idx = b * 256 + threadIdx.x;   // over MROWS*512/4
        if (idx >= MROWS * 128) return;
        float4 v = ((const float4*)x)[idx];
        uint4 r;
        r.x = tf32r(v.x); r.y = tf32r(v.y); r.z = tf32r(v.z); r.w = tf32r(v.w);
        ((uint4*)xt)[idx] = r;
    } else if (b < NXB + 1536) {
        const int n = b - NXB;
        const float* W = (n < 512) ? Wq : ((n < 1024) ? Wk : Wv);
        const int nc = n & 511;
        uint32_t* d = (uint32_t*)(w1t + (size_t)n * KDIM);
        for (int k = threadIdx.x; k < 512; k += 256)
            d[k] = tf32r(W[(size_t)k * 512 + nc]);
    } else {
        const int n = b - NXB - 1536;
        uint32_t* d = (uint32_t*)(w2t + (size_t)n * KDIM);
        for (int k = threadIdx.x; k < 512; k += 256)
            d[k] = tf32r(Wo[(size_t)k * 512 + n]);
    }
}

// ---------------------------------------------------------------------------
// Attention: one block per (head-pair, hw); 256 threads (128 per head).
// Outputs tf32-rounded fp32 [40960,512]. smem stride 65 -> conflict-free.
// ---------------------------------------------------------------------------
struct TrajTab { int hs[16]; int ws[16]; int subh, subw; };

#define APAD 65
__global__ __launch_bounds__(256) void attn_kernel(
    const float* __restrict__ qkv,
    const float* __restrict__ rel_k,
    const float* __restrict__ rel_v,
    float* __restrict__ att,
    TrajTab tt)
{
    const int h0 = blockIdx.x * 2;
    const int hw = blockIdx.y;
    const int tid = threadIdx.x;
    const int hh  = tid >> 7;
    const int sub = tid & 127;

    __shared__ float qs[2][16][APAD];
    __shared__ float ks[2][16][APAD];
    __shared__ float vs[2][16][APAD];
    __shared__ float rks[33][APAD];
    __shared__ float rvs[33][APAD];
    __shared__ float sim[2][16][17];
    __shared__ float attnw[2][16][17];

    const float* base = qkv + (size_t)hw * T_LEN * 1536 + (h0 + hh) * DHEAD;
    const int r  = sub >> 3;
    const int c0 = (sub & 7) * 8;

#pragma unroll
    for (int j = 0; j < 2; j++) {
        float4 a = *(const float4*)&base[(size_t)r * 1536 + c0 + 4 * j];
        float4 b = *(const float4*)&base[(size_t)r * 1536 + 512 + c0 + 4 * j];
        float4 c = *(const float4*)&base[(size_t)r * 1536 + 1024 + c0 + 4 * j];
        qs[hh][r][c0 + 4 * j + 0] = a.x; qs[hh][r][c0 + 4 * j + 1] = a.y;
        qs[hh][r][c0 + 4 * j + 2] = a.z; qs[hh][r][c0 + 4 * j + 3] = a.w;
        ks[hh][r][c0 + 4 * j + 0] = b.x; ks[hh][r][c0 + 4 * j + 1] = b.y;
        ks[hh][r][c0 + 4 * j + 2] = b.z; ks[hh][r][c0 + 4 * j + 3] = b.w;
        vs[hh][r][c0 + 4 * j + 0] = c.x; vs[hh][r][c0 + 4 * j + 1] = c.y;
        vs[hh][r][c0 + 4 * j + 2] = c.z; vs[hh][r][c0 + 4 * j + 3] = c.w;
    }
    for (int i = tid; i < 33 * 16; i += 256) {
        const int row = i >> 4, q4 = (i & 15) * 4;
        float4 a = ((const float4*)rel_k)[i];
        float4 b = ((const float4*)rel_v)[i];
        rks[row][q4 + 0] = a.x; rks[row][q4 + 1] = a.y;
        rks[row][q4 + 2] = a.z; rks[row][q4 + 3] = a.w;
        rvs[row][q4 + 0] = b.x; rvs[row][q4 + 1] = b.y;
        rvs[row][q4 + 2] = b.z; rvs[row][q4 + 3] = b.w;
    }

    // freetraj fg bitmask from host-computed tables
    const int y  = hw / 40;
    const int xx = hw % 40;
    unsigned fgm = 0;
#pragma unroll
    for (int i = 0; i < 16; i++) {
        if (y >= tt.hs[i] && y < tt.hs[i] + tt.subh &&
            xx >= tt.ws[i] && xx < tt.ws[i] + tt.subw)
            fgm |= (1u << i);
    }
    __syncthreads();

#pragma unroll
    for (int pp = 0; pp < 2; pp++) {
        const int p = sub + pp * 128;
        const int t = p >> 4, s = p & 15;
        const float* rk = rks[s - t + 16];
        float acc = 0.f;
#pragma unroll
        for (int d = 0; d < 64; d++)
            acc += qs[hh][t][d] * (ks[hh][s][d] + rk[d]);
        const float m = (((fgm >> t) & 1u) == ((fgm >> s) & 1u)) ? 1.0f : 0.01f;
        sim[hh][t][s] = acc * 0.125f * m;
    }
    __syncthreads();

    if (sub < 16) {
        float mx = -1e30f;
#pragma unroll
        for (int s = 0; s < 16; s++) mx = fmaxf(mx, sim[hh][sub][s]);
        float sum = 0.f;
#pragma unroll
        for (int s = 0; s < 16; s++) {
            float e = expf(sim[hh][sub][s] - mx);
            attnw[hh][sub][s] = e;
            sum += e;
        }
        float inv = 1.0f / sum;
#pragma unroll
        for (int s = 0; s < 16; s++) attnw[hh][sub][s] *= inv;
    }
    __syncthreads();

    const int t = r;
    float o[8];
#pragma unroll
    for (int j = 0; j < 8; j++) o[j] = 0.f;
#pragma unroll
    for (int s = 0; s < 16; s++) {
        const float a = attnw[hh][t][s];
        const float* rv = rvs[s - t + 16];
#pragma unroll
        for (int j = 0; j < 8; j++)
            o[j] += a * (vs[hh][s][c0 + j] + rv[c0 + j]);
    }

    // tf32-rounded fp32 store (GEMM2 consumes raw bits)
    uint4 p0, p1;
    p0.x = tf32r(o[0]); p0.y = tf32r(o[1]); p0.z = tf32r(o[2]); p0.w = tf32r(o[3]);
    p1.x = tf32r(o[4]); p1.y = tf32r(o[5]); p1.z = tf32r(o[6]); p1.w = tf32r(o[7]);
    uint32_t* op = (uint32_t*)(att + ((size_t)hw * T_LEN + t) * KDIM +
                               (h0 + hh) * DHEAD + c0);
    *(uint4*)(op)     = p0;
    *(uint4*)(op + 4) = p1;
}

// ---------------------------------------------------------------------------
extern "C" void kernel_launch(void* const* d_in, const int* in_sizes, int n_in,
                              void* d_out, int out_size)
{
    const float* x   = (const float*)d_in[0];
    const float* Wq  = (const float*)d_in[1];
    const float* Wk  = (const float*)d_in[2];
    const float* Wv  = (const float*)d_in[3];
    const float* Wo  = (const float*)d_in[4];
    const float* bo  = (const float*)d_in[5];
    const float* rk  = (const float*)d_in[6];
    const float* rv  = (const float*)d_in[7];
    float* out = (float*)d_out;

    float *qkv = nullptr, *xt = nullptr, *att = nullptr, *w1t = nullptr, *w2t = nullptr;
    cudaGetSymbolAddress((void**)&qkv, g_qkv);
    cudaGetSymbolAddress((void**)&xt,  g_xt);
    cudaGetSymbolAddress((void**)&att, g_att);
    cudaGetSymbolAddress((void**)&w1t, g_w1t);
    cudaGetSymbolAddress((void**)&w2t, g_w2t);

    cudaFuncSetAttribute(mma_gemm, cudaFuncAttributeMaxDynamicSharedMemorySize,
                         SMEM_TOTAL);

    // host-side trajectory tables (exact Python double semantics)
    TrajTab tt;
    tt.subh = (int)((0.35 - 0.10) * 64.0);   // 15
    tt.subw = (int)((0.35 - 0.10) * 40.0);   // 9
    for (int i = 0; i < 16; i++) {
        double rr = (double)i / 15.0;
        double ph = 0.10 + rr * (0.60 - 0.10);
        double pw = 0.10 + rr * (0.60 - 0.10);
        tt.hs[i] = (int)(ph * 64.0);
        tt.ws[i] = (int)(pw * 40.0);
    }

    // prep: tf32 rounding + weight transposes (one launch)
    prep_all<<<NXB + 1536 + 512, 256>>>(x, Wq, Wk, Wv, Wo, xt, w1t, w2t);

    // QKV projection: [40960,1536] = xt @ w1t^T
    mma_gemm<<<dim3(1536 / BN, MROWS / BM), 256, SMEM_TOTAL>>>(
        xt, w1t, nullptr, qkv, 1536);

    // attention (2 heads per block)
    attn_kernel<<<dim3(NHEAD / 2, HW_N), 256>>>(qkv, rk, rv, att, tt);

    // output projection: [40960,512] = att @ w2t^T + bo
    mma_gemm<<<dim3(512 / BN, MROWS / BM), 256, SMEM_TOTAL>>>(
        att, w2t, bo, out, 512);
}